// round 6
// baseline (speedup 1.0000x reference)
#include <cuda_runtime.h>
#include <cuda_bf16.h>
#include <mma.h>
#include <math.h>
#include <cstdint>

using namespace nvcuda;

// ---------------- problem constants ----------------
#define BB   128
#define TT   256
#define TC   200
#define EE   256
#define HH   512
#define H4   2048
#define VV   50000
#define MAX_OOV 50
#define VEXT 50050
#define LPAD 50176   // padded logits row stride

#define ASTR 36      // smem row stride in floats (32 + 4 pad)

// ---------------- scratch (device globals; no allocation) ----------------
__device__ float g_gates[BB * H4];
__device__ float g_dec2[BB * 1024];        // [dec | cdec] per row
__device__ float g_context[BB * HH];
__device__ float g_cctx[BB * HH];
__device__ float g_scores[2][BB][TT];      // attn 0/1 scores (raw then normalized)
__device__ float g_pgen[BB];
__device__ float g_logits[BB * LPAD];

__device__ __forceinline__ float sigmoidf_(float x) {
    return 1.0f / (1.0f + __expf(-x));
}

// ---------------- cp.async helpers ----------------
__device__ __forceinline__ void cp_async16(uint32_t dst, const void* src) {
    asm volatile("cp.async.cg.shared.global [%0], [%1], 16;\n" :: "r"(dst), "l"(src));
}
__device__ __forceinline__ void cp_commit() {
    asm volatile("cp.async.commit_group;\n" ::);
}
template <int N>
__device__ __forceinline__ void cp_wait() {
    asm volatile("cp.async.wait_group %0;\n" :: "n"(N));
}

// block reduce: op 0 = max, 1 = sum
__device__ __forceinline__ float block_reduce(float v, float* red, int op) {
    int lane = threadIdx.x & 31, warp = threadIdx.x >> 5;
    #pragma unroll
    for (int o = 16; o > 0; o >>= 1) {
        float u = __shfl_xor_sync(0xffffffffu, v, o);
        v = op ? (v + u) : fmaxf(v, u);
    }
    if (lane == 0) red[warp] = v;
    __syncthreads();
    int nw = (blockDim.x + 31) >> 5;
    if (warp == 0) {
        v = (lane < nw) ? red[lane] : (op ? 0.0f : -INFINITY);
        #pragma unroll
        for (int o = 16; o > 0; o >>= 1) {
            float u = __shfl_xor_sync(0xffffffffu, v, o);
            v = op ? (v + u) : fmaxf(v, u);
        }
        if (lane == 0) red[0] = v;
    }
    __syncthreads();
    float r = red[0];
    __syncthreads();
    return r;
}

// ============================================================================
// tf32 tensor-core GEMM: C[128, N] = A[128, K] * W[N, K]^T
//   256 threads (8 warps, 4x2), warp tile 32 x BN/2, cp.async double buffer.
//   A K-concat: k < K1 -> A1 (optional row gather), else A2 at k-K1.
//   W K-concat: k < K1 -> W1, else W2.  W N-split: rows >= Nsplit -> Wn2.
//   W rows clamped to N-1 (pad cols are dups; downstream ignores them).
// ============================================================================
template <int BN>
__global__ void __launch_bounds__(256, 2)
gemm_tc(const float* __restrict__ A1, int lda1,
        const float* __restrict__ A2, int lda2,
        const int* __restrict__ gather_idx,
        const float* __restrict__ W1, int ldw1,
        const float* __restrict__ W2, int ldw2, int K1,
        const float* __restrict__ Wn2, int ldwn2, int Nsplit,
        float* __restrict__ C, int ldc,
        int N, int K) {
    extern __shared__ float smem[];
    float* As = smem;                    // 2 stages x 128 x ASTR
    float* Ws = smem + 2 * 128 * ASTR;   // 2 stages x BN  x ASTR

    const int tid = threadIdx.x;
    const int wid = tid >> 5;
    const int warp_m = wid >> 1;         // 0..3 -> 32-row slab
    const int warp_n = wid & 1;          // 0..1 -> BN/2-col slab
    const int n0 = blockIdx.x * BN;
    constexpr int WN = BN / 2;
    constexpr int NI = WN / 16;          // 4 (BN=128) or 2 (BN=64)
    const int KT = K >> 5;

    const uint32_t as_base = (uint32_t)__cvta_generic_to_shared(As);
    const uint32_t ws_base = (uint32_t)__cvta_generic_to_shared(Ws);

    auto issue_stage = [&](int kt, int s) {
        const int kk = kt << 5;
        #pragma unroll
        for (int r = 0; r < 4; r++) {            // A: 1024 float4 / 256 thr
            int f = tid + r * 256;
            int row = f >> 3, kq = f & 7;
            int k = kk + kq * 4;
            const float* src;
            if (k < K1) {
                int arow = gather_idx ? gather_idx[row] : row;
                src = A1 + (size_t)arow * lda1 + k;
            } else {
                src = A2 + (size_t)row * lda2 + (k - K1);
            }
            cp_async16(as_base + (uint32_t)((s * 128 + row) * ASTR + kq * 4) * 4, src);
        }
        #pragma unroll
        for (int r = 0; r < BN / 32; r++) {      // W: BN*8 float4 / 256 thr
            int f = tid + r * 256;
            int row = f >> 3, kq = f & 7;
            int k = kk + kq * 4;
            int nr = n0 + row;
            if (nr >= N) nr = N - 1;
            const float* src;
            if (k < K1) {
                if (Wn2 && nr >= Nsplit)
                    src = Wn2 + (size_t)(nr - Nsplit) * ldwn2 + k;
                else
                    src = W1 + (size_t)nr * ldw1 + k;
            } else {
                src = W2 + (size_t)nr * ldw2 + (k - K1);
            }
            cp_async16(ws_base + (uint32_t)((s * BN + row) * ASTR + kq * 4) * 4, src);
        }
        cp_commit();
    };

    wmma::fragment<wmma::accumulator, 16, 16, 8, float> c[2][NI];
    #pragma unroll
    for (int i = 0; i < 2; i++)
        #pragma unroll
        for (int j = 0; j < NI; j++) wmma::fill_fragment(c[i][j], 0.0f);

    issue_stage(0, 0);

    for (int kt = 0; kt < KT; kt++) {
        if (kt + 1 < KT) {
            issue_stage(kt + 1, (kt + 1) & 1);
            cp_wait<1>();
        } else {
            cp_wait<0>();
        }
        __syncthreads();

        const int s = kt & 1;
        const float* as = As + (size_t)s * 128 * ASTR;
        const float* ws = Ws + (size_t)s * BN * ASTR;

        #pragma unroll
        for (int k8 = 0; k8 < 32; k8 += 8) {
            wmma::fragment<wmma::matrix_a, 16, 16, 8, wmma::precision::tf32,
                           wmma::row_major> a[2];
            wmma::fragment<wmma::matrix_b, 16, 16, 8, wmma::precision::tf32,
                           wmma::col_major> b[NI];
            #pragma unroll
            for (int mi = 0; mi < 2; mi++)
                wmma::load_matrix_sync(a[mi],
                    as + (warp_m * 32 + mi * 16) * ASTR + k8, ASTR);
            #pragma unroll
            for (int ni = 0; ni < NI; ni++)
                wmma::load_matrix_sync(b[ni],
                    ws + (warp_n * WN + ni * 16) * ASTR + k8, ASTR);
            #pragma unroll
            for (int mi = 0; mi < 2; mi++)
                #pragma unroll
                for (int ni = 0; ni < NI; ni++)
                    wmma::mma_sync(c[mi][ni], a[mi], b[ni], c[mi][ni]);
        }
        __syncthreads();
    }

    #pragma unroll
    for (int mi = 0; mi < 2; mi++)
        #pragma unroll
        for (int ni = 0; ni < NI; ni++)
            wmma::store_matrix_sync(
                &C[(size_t)(warp_m * 32 + mi * 16) * ldc + n0 + warp_n * WN + ni * 16],
                c[mi][ni], ldc, wmma::mem_row_major);
}

// ---------------- LSTM pointwise ----------------
__global__ void lstm_kernel(const float* __restrict__ c0,
                            const float* __restrict__ b_ih,
                            const float* __restrict__ b_hh,
                            float* __restrict__ h1_out,
                            float* __restrict__ c1_out) {
    int i = blockIdx.x * blockDim.x + threadIdx.x;  // B*H
    if (i >= BB * HH) return;
    int b = i / HH, h = i % HH;
    const float* g = g_gates + (size_t)b * H4;
    float gi = g[h]          + b_ih[h]          + b_hh[h];
    float gf = g[HH + h]     + b_ih[HH + h]     + b_hh[HH + h];
    float gg = g[2 * HH + h] + b_ih[2 * HH + h] + b_hh[2 * HH + h];
    float go = g[3 * HH + h] + b_ih[3 * HH + h] + b_hh[3 * HH + h];
    float c = sigmoidf_(gf) * c0[i] + sigmoidf_(gi) * tanhf(gg);
    float hh = sigmoidf_(go) * tanhf(c);
    c1_out[i] = c;
    h1_out[i] = hh;
}

// ---------------- attention scores (raw): grid (8, B, 2), 128 threads ----------------
__global__ void scores_kernel(const float* __restrict__ enc,
                              const float* __restrict__ cenc,
                              const float* __restrict__ attn_b,
                              const float* __restrict__ cattn_b) {
    const int aid = blockIdx.z;
    const int b = blockIdx.y;
    const int t0 = blockIdx.x * 32;
    const int T = aid ? TC : TT;
    if (t0 >= T) return;

    __shared__ float sdec[HH];
    const int tid = threadIdx.x;  // 128
    {
        const float* dec = g_dec2 + (size_t)b * 1024 + aid * HH;
        const float* bias = aid ? cattn_b : attn_b;
        #pragma unroll
        for (int i = 0; i < 4; i++)
            sdec[tid + i * 128] = dec[tid + i * 128] + bias[tid + i * 128];
    }
    __syncthreads();

    const float* eb = (aid ? cenc : enc) + (size_t)b * T * HH;
    const int warp = tid >> 5, lane = tid & 31;

    #pragma unroll
    for (int j = 0; j < 8; j++) {
        int t = t0 + warp * 8 + j;
        if (t < T) {
            const float4* row = reinterpret_cast<const float4*>(eb + (size_t)t * HH);
            float s = 0.0f;
            #pragma unroll
            for (int q = 0; q < 4; q++) {
                int f4 = lane + 32 * q;
                float4 v = row[f4];
                s += v.x * sdec[f4 * 4 + 0] + v.y * sdec[f4 * 4 + 1] +
                     v.z * sdec[f4 * 4 + 2] + v.w * sdec[f4 * 4 + 3];
            }
            #pragma unroll
            for (int o = 16; o > 0; o >>= 1) s += __shfl_xor_sync(0xffffffffu, s, o);
            if (lane == 0) g_scores[aid][b][t] = s;
        }
    }
}

// ---------------- per-row score softmax: grid (B, 2), 256 threads ----------------
__global__ void score_softmax_kernel() {
    const int b = blockIdx.x;
    const int aid = blockIdx.y;
    const int T = aid ? TC : TT;
    const int tid = threadIdx.x;  // 256
    __shared__ float red[32];
    float* sc = g_scores[aid][b];

    float v = (tid < T) ? sc[tid] : -INFINITY;
    float m = block_reduce(v, red, 0);
    float e = (tid < T) ? __expf(v - m) : 0.0f;
    float s = block_reduce(e, red, 1);
    if (tid < T) sc[tid] = e / s;
}

// ---------------- attention context: grid (4, B, 2), 128 threads ----------------
__global__ void ctx_kernel(const float* __restrict__ enc,
                           const float* __restrict__ cenc) {
    const int hc = blockIdx.x;      // 0..3 -> 128 h each
    const int b = blockIdx.y;
    const int aid = blockIdx.z;
    const int T = aid ? TC : TT;
    const int tid = threadIdx.x;    // 128

    __shared__ float sw[TT];
    for (int t = tid; t < T; t += 128) sw[t] = g_scores[aid][b][t];
    __syncthreads();

    const float* eb = (aid ? cenc : enc) + (size_t)b * T * HH + hc * 128 + tid;
    float acc = 0.0f;
    int t = 0;
    for (; t + 4 <= T; t += 4) {
        float x0 = eb[(size_t)(t + 0) * HH];
        float x1 = eb[(size_t)(t + 1) * HH];
        float x2 = eb[(size_t)(t + 2) * HH];
        float x3 = eb[(size_t)(t + 3) * HH];
        acc += sw[t] * x0 + sw[t + 1] * x1 + sw[t + 2] * x2 + sw[t + 3] * x3;
    }
    for (; t < T; t++) acc += sw[t] * eb[(size_t)t * HH];

    float* dst = aid ? g_cctx : g_context;
    dst[(size_t)b * HH + hc * 128 + tid] = acc;
}

// ---------------- p_gen ----------------
__global__ void pgen_kernel(const float* __restrict__ h1,
                            const float* __restrict__ embedding,
                            const int* __restrict__ input,
                            const float* __restrict__ gen_W,
                            const float* __restrict__ gen_b,
                            const float* __restrict__ sig_b,
                            const int* __restrict__ context_input) {
    __shared__ float red[32];
    int b = blockIdx.x;
    int tid = threadIdx.x;  // 256
    float s = 0.0f;
    for (int k = tid; k < HH; k += 256) s += g_context[b * HH + k] * gen_W[k];
    for (int k = tid; k < HH; k += 256) s += g_cctx[b * HH + k] * gen_W[HH + k];
    for (int k = tid; k < HH; k += 256) s += h1[b * HH + k] * gen_W[2 * HH + k];
    {
        const float* emb = embedding + (size_t)input[b] * EE;
        for (int k = tid; k < EE; k += 256) s += emb[k] * gen_W[3 * HH + k];
    }
    s = block_reduce(s, red, 1);

    float cnt = 0.0f;
    for (int t = tid; t < TC; t += 256)
        cnt += (context_input[(size_t)b * TC + t] > 0) ? 1.0f : 0.0f;
    cnt = block_reduce(cnt, red, 1);

    if (tid == 0) {
        float p = sigmoidf_(s + gen_b[0] + sig_b[0]);
        if (cnt == 0.0f) p = 1.0f;
        g_pgen[b] = p;
    }
}

// ---------------- fused tail: softmax + copy-scatter + log -> d_out ----------------
// grid (B), 256 threads, smem: copyv[VEXT] + red[32]
__global__ void final_kernel(const float* __restrict__ out_b,
                             const int* __restrict__ context_input,
                             float* __restrict__ out) {
    extern __shared__ float sm[];
    float* copyv = sm;            // VEXT floats
    float* red = sm + VEXT;       // 32 floats
    const int b = blockIdx.x;
    const int tid = threadIdx.x;  // 256

    for (int v = tid; v < VEXT; v += 256) copyv[v] = 0.0f;
    __syncthreads();

    const float pg = g_pgen[b];
    if (tid < TC) {
        int idx = context_input[(size_t)b * TC + tid];
        float w = (1.0f - pg) * g_scores[1][b][tid];
        atomicAdd(&copyv[idx], w);
    }
    __syncthreads();

    const float* lg = g_logits + (size_t)b * LPAD;
    float* row = out + (size_t)b * VEXT;

    // online (m, s) over logits + bias
    float m = -INFINITY, s = 0.0f;
    for (int v = tid; v < VV; v += 256) {
        float x = lg[v] + out_b[v];
        if (x > m) {
            s = s * __expf(m - x) + 1.0f;
            m = x;
        } else {
            s += __expf(x - m);
        }
    }
    float M = block_reduce(m, red, 0);
    s = (m == -INFINITY) ? 0.0f : s * __expf(m - M);
    float S = block_reduce(s, red, 1);
    const float scale = pg / S;

    for (int v = tid; v < VV; v += 256) {
        float p = __expf(lg[v] + out_b[v] - M) * scale + copyv[v];
        row[v] = __logf(fmaxf(p, 1e-10f));
    }
    for (int v = VV + tid; v < VEXT; v += 256)
        row[v] = __logf(fmaxf(copyv[v], 1e-10f));
}

// ---------------- launcher ----------------
extern "C" void kernel_launch(void* const* d_in, const int* in_sizes, int n_in,
                              void* d_out, int out_size) {
    const int*   input    = (const int*)  d_in[0];
    const float* h0       = (const float*)d_in[1];
    const float* c0       = (const float*)d_in[2];
    const float* enc      = (const float*)d_in[3];
    const float* cenc     = (const float*)d_in[4];
    const int*   ctx_in   = (const int*)  d_in[5];
    const float* embedding= (const float*)d_in[6];
    const float* W_ih     = (const float*)d_in[7];
    const float* W_hh     = (const float*)d_in[8];
    const float* b_ih     = (const float*)d_in[9];
    const float* b_hh     = (const float*)d_in[10];
    const float* attn_W   = (const float*)d_in[11];
    const float* attn_b   = (const float*)d_in[12];
    const float* cattn_W  = (const float*)d_in[13];
    const float* cattn_b  = (const float*)d_in[14];
    const float* gen_W    = (const float*)d_in[15];
    const float* gen_b    = (const float*)d_in[16];
    const float* sig_b    = (const float*)d_in[17];
    const float* out_W    = (const float*)d_in[18];
    const float* out_b    = (const float*)d_in[19];

    float* out = (float*)d_out;
    float* logp   = out;
    float* h1_out = out + (size_t)BB * VEXT;
    float* c1_out = h1_out + (size_t)BB * HH;

    float* d_gates;  cudaGetSymbolAddress((void**)&d_gates,  g_gates);
    float* d_dec2;   cudaGetSymbolAddress((void**)&d_dec2,   g_dec2);
    float* d_logits; cudaGetSymbolAddress((void**)&d_logits, g_logits);

    const int SMEM128 = (2 * 128 * ASTR + 2 * 128 * ASTR) * 4;  // 73728
    const int SMEM64  = (2 * 128 * ASTR + 2 * 64  * ASTR) * 4;  // 55296
    const int SMEM_FINAL = (VEXT + 32) * 4;                      // 200328
    cudaFuncSetAttribute(gemm_tc<128>,
        cudaFuncAttributeMaxDynamicSharedMemorySize, SMEM128);
    cudaFuncSetAttribute(gemm_tc<64>,
        cudaFuncAttributeMaxDynamicSharedMemorySize, SMEM64);
    cudaFuncSetAttribute(final_kernel,
        cudaFuncAttributeMaxDynamicSharedMemorySize, SMEM_FINAL);

    // 1) gates = [emb | h0] @ [W_ih | W_hh]^T   (K=768, K1=256, emb gathered)
    gemm_tc<64><<<H4 / 64, 256, SMEM64>>>(
        embedding, EE, h0, HH, input,
        W_ih, EE, W_hh, HH, EE,
        nullptr, 0, 0,
        d_gates, H4, H4, EE + HH);

    // 2) LSTM pointwise -> h1, c1 (into d_out tail)
    lstm_kernel<<<(BB * HH + 255) / 256, 256>>>(c0, b_ih, b_hh, h1_out, c1_out);

    // 3) [dec | cdec] = h1 @ [attn_W ; cattn_W]^T   (N=1024, N-split at 512)
    gemm_tc<64><<<1024 / 64, 256, SMEM64>>>(
        h1_out, HH, h1_out, HH, nullptr,
        attn_W, HH, attn_W, HH, HH,
        cattn_W, HH, HH,
        d_dec2, 1024, 1024, HH);

    // 4) BIG: logits = h1 @ out_W^T  (ncu slot)
    gemm_tc<128><<<LPAD / 128, 256, SMEM128>>>(
        h1_out, HH, h1_out, HH, nullptr,
        out_W, HH, out_W, HH, HH,
        nullptr, 0, 0,
        d_logits, LPAD, VV, HH);

    // 5) attention scores (both attns)
    scores_kernel<<<dim3(8, BB, 2), 128>>>(enc, cenc, attn_b, cattn_b);

    // 6) score softmax (both attns)
    score_softmax_kernel<<<dim3(BB, 2), 256>>>();

    // 7) contexts (both attns)
    ctx_kernel<<<dim3(4, BB, 2), 128>>>(enc, cenc);

    // 8) p_gen
    pgen_kernel<<<BB, 256>>>(h1_out, embedding, input, gen_W, gen_b, sig_b, ctx_in);

    // 9) fused softmax + scatter + log -> d_out
    final_kernel<<<BB, 256, SMEM_FINAL>>>(out_b, ctx_in, logp);
}

// round 7
// speedup vs baseline: 1.1448x; 1.1448x over previous
#include <cuda_runtime.h>
#include <cuda_bf16.h>
#include <mma.h>
#include <math.h>
#include <cstdint>

using namespace nvcuda;

// ---------------- problem constants ----------------
#define BB   128
#define TT   256
#define TC   200
#define EE   256
#define HH   512
#define H4   2048
#define VV   50000
#define MAX_OOV 50
#define VEXT 50050
#define LPAD 50176   // padded logits row stride
#define VHALF 25024  // V-range split for write_kernel (half1 len = 25026)

#define ASTR 36      // smem row stride in floats (32 + 4 pad)
#define NSTG 3       // cp.async pipeline stages

// ---------------- scratch (device globals; no allocation) ----------------
__device__ float g_gates[BB * H4];
__device__ float g_dec2[BB * 1024];        // [dec | cdec] per row
__device__ float g_context[BB * HH];
__device__ float g_cctx[BB * HH];
__device__ float g_scores[2][BB][TT];      // attn 0/1 scores (raw then normalized)
__device__ float g_pgen[BB];
__device__ float g_stats[BB * 2];          // {M, pgen/S} per row
__device__ float g_logits[BB * LPAD];

__device__ __forceinline__ float sigmoidf_(float x) {
    return 1.0f / (1.0f + __expf(-x));
}

// ---------------- cp.async helpers ----------------
__device__ __forceinline__ void cp_async16(uint32_t dst, const void* src) {
    asm volatile("cp.async.cg.shared.global [%0], [%1], 16;\n" :: "r"(dst), "l"(src));
}
__device__ __forceinline__ void cp_commit() {
    asm volatile("cp.async.commit_group;\n" ::);
}
template <int N>
__device__ __forceinline__ void cp_wait() {
    asm volatile("cp.async.wait_group %0;\n" :: "n"(N));
}

// block reduce: op 0 = max, 1 = sum (blockDim <= 1024)
__device__ __forceinline__ float block_reduce(float v, float* red, int op) {
    int lane = threadIdx.x & 31, warp = threadIdx.x >> 5;
    #pragma unroll
    for (int o = 16; o > 0; o >>= 1) {
        float u = __shfl_xor_sync(0xffffffffu, v, o);
        v = op ? (v + u) : fmaxf(v, u);
    }
    if (lane == 0) red[warp] = v;
    __syncthreads();
    int nw = (blockDim.x + 31) >> 5;
    if (warp == 0) {
        v = (lane < nw) ? red[lane] : (op ? 0.0f : -INFINITY);
        #pragma unroll
        for (int o = 16; o > 0; o >>= 1) {
            float u = __shfl_xor_sync(0xffffffffu, v, o);
            v = op ? (v + u) : fmaxf(v, u);
        }
        if (lane == 0) red[0] = v;
    }
    __syncthreads();
    float r = red[0];
    __syncthreads();
    return r;
}

// ============================================================================
// tf32 tensor-core GEMM: C[128, N] = A[128, K] * W[N, K]^T
//   256 threads (8 warps, 4x2), warp tile 32 x BN/2, 3-stage cp.async pipeline.
//   A K-concat: k < K1 -> A1 (optional row gather), else A2 at k-K1.
//   W K-concat: k < K1 -> W1, else W2.  W N-split: rows >= Nsplit -> Wn2.
//   W rows clamped to N-1 (pad cols are dups; downstream ignores them).
// ============================================================================
template <int BN>
__global__ void __launch_bounds__(256, 2)
gemm_tc(const float* __restrict__ A1, int lda1,
        const float* __restrict__ A2, int lda2,
        const int* __restrict__ gather_idx,
        const float* __restrict__ W1, int ldw1,
        const float* __restrict__ W2, int ldw2, int K1,
        const float* __restrict__ Wn2, int ldwn2, int Nsplit,
        float* __restrict__ C, int ldc,
        int N, int K) {
    extern __shared__ float smem[];
    float* As = smem;                        // NSTG stages x 128 x ASTR
    float* Ws = smem + NSTG * 128 * ASTR;    // NSTG stages x BN  x ASTR

    const int tid = threadIdx.x;
    const int wid = tid >> 5;
    const int warp_m = wid >> 1;             // 0..3 -> 32-row slab
    const int warp_n = wid & 1;              // 0..1 -> BN/2-col slab
    const int n0 = blockIdx.x * BN;
    constexpr int WN = BN / 2;
    constexpr int NI = WN / 16;
    const int KT = K >> 5;

    const uint32_t as_base = (uint32_t)__cvta_generic_to_shared(As);
    const uint32_t ws_base = (uint32_t)__cvta_generic_to_shared(Ws);

    auto issue_stage = [&](int kt, int s) {
        const int kk = kt << 5;
        #pragma unroll
        for (int r = 0; r < 4; r++) {            // A: 1024 float4 / 256 thr
            int f = tid + r * 256;
            int row = f >> 3, kq = f & 7;
            int k = kk + kq * 4;
            const float* src;
            if (k < K1) {
                int arow = gather_idx ? gather_idx[row] : row;
                src = A1 + (size_t)arow * lda1 + k;
            } else {
                src = A2 + (size_t)row * lda2 + (k - K1);
            }
            cp_async16(as_base + (uint32_t)((s * 128 + row) * ASTR + kq * 4) * 4, src);
        }
        #pragma unroll
        for (int r = 0; r < BN / 32; r++) {      // W: BN*8 float4 / 256 thr
            int f = tid + r * 256;
            int row = f >> 3, kq = f & 7;
            int k = kk + kq * 4;
            int nr = n0 + row;
            if (nr >= N) nr = N - 1;
            const float* src;
            if (k < K1) {
                if (Wn2 && nr >= Nsplit)
                    src = Wn2 + (size_t)(nr - Nsplit) * ldwn2 + k;
                else
                    src = W1 + (size_t)nr * ldw1 + k;
            } else {
                src = W2 + (size_t)nr * ldw2 + (k - K1);
            }
            cp_async16(ws_base + (uint32_t)((s * BN + row) * ASTR + kq * 4) * 4, src);
        }
        cp_commit();
    };

    wmma::fragment<wmma::accumulator, 16, 16, 8, float> c[2][NI];
    #pragma unroll
    for (int i = 0; i < 2; i++)
        #pragma unroll
        for (int j = 0; j < NI; j++) wmma::fill_fragment(c[i][j], 0.0f);

    issue_stage(0, 0);
    if (KT > 1) issue_stage(1, 1);

    for (int kt = 0; kt < KT; kt++) {
        if (kt + 2 < KT) {
            issue_stage(kt + 2, (kt + 2) % NSTG);
            cp_wait<2>();
        } else if (kt + 1 < KT) {
            cp_wait<1>();
        } else {
            cp_wait<0>();
        }
        __syncthreads();

        const int s = kt % NSTG;
        const float* as = As + (size_t)s * 128 * ASTR;
        const float* ws = Ws + (size_t)s * BN * ASTR;

        #pragma unroll
        for (int k8 = 0; k8 < 32; k8 += 8) {
            wmma::fragment<wmma::matrix_a, 16, 16, 8, wmma::precision::tf32,
                           wmma::row_major> a[2];
            wmma::fragment<wmma::matrix_b, 16, 16, 8, wmma::precision::tf32,
                           wmma::col_major> b[NI];
            #pragma unroll
            for (int mi = 0; mi < 2; mi++)
                wmma::load_matrix_sync(a[mi],
                    as + (warp_m * 32 + mi * 16) * ASTR + k8, ASTR);
            #pragma unroll
            for (int ni = 0; ni < NI; ni++)
                wmma::load_matrix_sync(b[ni],
                    ws + (warp_n * WN + ni * 16) * ASTR + k8, ASTR);
            #pragma unroll
            for (int mi = 0; mi < 2; mi++)
                #pragma unroll
                for (int ni = 0; ni < NI; ni++)
                    wmma::mma_sync(c[mi][ni], a[mi], b[ni], c[mi][ni]);
        }
        __syncthreads();
    }

    #pragma unroll
    for (int mi = 0; mi < 2; mi++)
        #pragma unroll
        for (int ni = 0; ni < NI; ni++)
            wmma::store_matrix_sync(
                &C[(size_t)(warp_m * 32 + mi * 16) * ldc + n0 + warp_n * WN + ni * 16],
                c[mi][ni], ldc, wmma::mem_row_major);
}

// ---------------- LSTM pointwise ----------------
__global__ void lstm_kernel(const float* __restrict__ c0,
                            const float* __restrict__ b_ih,
                            const float* __restrict__ b_hh,
                            float* __restrict__ h1_out,
                            float* __restrict__ c1_out) {
    int i = blockIdx.x * blockDim.x + threadIdx.x;  // B*H
    if (i >= BB * HH) return;
    int b = i / HH, h = i % HH;
    const float* g = g_gates + (size_t)b * H4;
    float gi = g[h]          + b_ih[h]          + b_hh[h];
    float gf = g[HH + h]     + b_ih[HH + h]     + b_hh[HH + h];
    float gg = g[2 * HH + h] + b_ih[2 * HH + h] + b_hh[2 * HH + h];
    float go = g[3 * HH + h] + b_ih[3 * HH + h] + b_hh[3 * HH + h];
    float c = sigmoidf_(gf) * c0[i] + sigmoidf_(gi) * tanhf(gg);
    float hh = sigmoidf_(go) * tanhf(c);
    c1_out[i] = c;
    h1_out[i] = hh;
}

// ---------------- attention scores (raw): grid (8, B, 2), 128 threads ----------------
__global__ void scores_kernel(const float* __restrict__ enc,
                              const float* __restrict__ cenc,
                              const float* __restrict__ attn_b,
                              const float* __restrict__ cattn_b) {
    const int aid = blockIdx.z;
    const int b = blockIdx.y;
    const int t0 = blockIdx.x * 32;
    const int T = aid ? TC : TT;
    if (t0 >= T) return;

    __shared__ float sdec[HH];
    const int tid = threadIdx.x;  // 128
    {
        const float* dec = g_dec2 + (size_t)b * 1024 + aid * HH;
        const float* bias = aid ? cattn_b : attn_b;
        #pragma unroll
        for (int i = 0; i < 4; i++)
            sdec[tid + i * 128] = dec[tid + i * 128] + bias[tid + i * 128];
    }
    __syncthreads();

    const float* eb = (aid ? cenc : enc) + (size_t)b * T * HH;
    const int warp = tid >> 5, lane = tid & 31;

    #pragma unroll
    for (int j = 0; j < 8; j++) {
        int t = t0 + warp * 8 + j;
        if (t < T) {
            const float4* row = reinterpret_cast<const float4*>(eb + (size_t)t * HH);
            float s = 0.0f;
            #pragma unroll
            for (int q = 0; q < 4; q++) {
                int f4 = lane + 32 * q;
                float4 v = row[f4];
                s += v.x * sdec[f4 * 4 + 0] + v.y * sdec[f4 * 4 + 1] +
                     v.z * sdec[f4 * 4 + 2] + v.w * sdec[f4 * 4 + 3];
            }
            #pragma unroll
            for (int o = 16; o > 0; o >>= 1) s += __shfl_xor_sync(0xffffffffu, s, o);
            if (lane == 0) g_scores[aid][b][t] = s;
        }
    }
}

// ---------------- per-row score softmax: grid (B, 2), 256 threads ----------------
__global__ void score_softmax_kernel() {
    const int b = blockIdx.x;
    const int aid = blockIdx.y;
    const int T = aid ? TC : TT;
    const int tid = threadIdx.x;  // 256
    __shared__ float red[32];
    float* sc = g_scores[aid][b];

    float v = (tid < T) ? sc[tid] : -INFINITY;
    float m = block_reduce(v, red, 0);
    float e = (tid < T) ? __expf(v - m) : 0.0f;
    float s = block_reduce(e, red, 1);
    if (tid < T) sc[tid] = e / s;
}

// ---------------- attention context: grid (4, B, 2), 128 threads ----------------
__global__ void ctx_kernel(const float* __restrict__ enc,
                           const float* __restrict__ cenc) {
    const int hc = blockIdx.x;      // 0..3 -> 128 h each
    const int b = blockIdx.y;
    const int aid = blockIdx.z;
    const int T = aid ? TC : TT;
    const int tid = threadIdx.x;    // 128

    __shared__ float sw[TT];
    for (int t = tid; t < T; t += 128) sw[t] = g_scores[aid][b][t];
    __syncthreads();

    const float* eb = (aid ? cenc : enc) + (size_t)b * T * HH + hc * 128 + tid;
    float acc = 0.0f;
    int t = 0;
    for (; t + 4 <= T; t += 4) {
        float x0 = eb[(size_t)(t + 0) * HH];
        float x1 = eb[(size_t)(t + 1) * HH];
        float x2 = eb[(size_t)(t + 2) * HH];
        float x3 = eb[(size_t)(t + 3) * HH];
        acc += sw[t] * x0 + sw[t + 1] * x1 + sw[t + 2] * x2 + sw[t + 3] * x3;
    }
    for (; t < T; t++) acc += sw[t] * eb[(size_t)t * HH];

    float* dst = aid ? g_cctx : g_context;
    dst[(size_t)b * HH + hc * 128 + tid] = acc;
}

// ---------------- p_gen ----------------
__global__ void pgen_kernel(const float* __restrict__ h1,
                            const float* __restrict__ embedding,
                            const int* __restrict__ input,
                            const float* __restrict__ gen_W,
                            const float* __restrict__ gen_b,
                            const float* __restrict__ sig_b,
                            const int* __restrict__ context_input) {
    __shared__ float red[32];
    int b = blockIdx.x;
    int tid = threadIdx.x;  // 256
    float s = 0.0f;
    for (int k = tid; k < HH; k += 256) s += g_context[b * HH + k] * gen_W[k];
    for (int k = tid; k < HH; k += 256) s += g_cctx[b * HH + k] * gen_W[HH + k];
    for (int k = tid; k < HH; k += 256) s += h1[b * HH + k] * gen_W[2 * HH + k];
    {
        const float* emb = embedding + (size_t)input[b] * EE;
        for (int k = tid; k < EE; k += 256) s += emb[k] * gen_W[3 * HH + k];
    }
    s = block_reduce(s, red, 1);

    float cnt = 0.0f;
    for (int t = tid; t < TC; t += 256)
        cnt += (context_input[(size_t)b * TC + t] > 0) ? 1.0f : 0.0f;
    cnt = block_reduce(cnt, red, 1);

    if (tid == 0) {
        float p = sigmoidf_(s + gen_b[0] + sig_b[0]);
        if (cnt == 0.0f) p = 1.0f;
        g_pgen[b] = p;
    }
}

// ---------------- stats: per-row softmax max + scale: grid (B), 512 thr ----------------
__global__ void stats_kernel(const float* __restrict__ out_b) {
    __shared__ float red[32];
    const int b = blockIdx.x;
    const int tid = threadIdx.x;  // 512
    const float* lg = g_logits + (size_t)b * LPAD;

    float m = -INFINITY, s = 0.0f;
    for (int v = tid; v < VV; v += 512) {
        float x = lg[v] + out_b[v];
        if (x > m) {
            s = s * __expf(m - x) + 1.0f;
            m = x;
        } else {
            s += __expf(x - m);
        }
    }
    float M = block_reduce(m, red, 0);
    s = (m == -INFINITY) ? 0.0f : s * __expf(m - M);
    float S = block_reduce(s, red, 1);

    if (tid == 0) {
        g_stats[b * 2 + 0] = M;
        g_stats[b * 2 + 1] = g_pgen[b] / S;
    }
}

// ---------------- write: half-V-range prob + copy + log: grid (2, B), 256 thr ----------------
__global__ void write_kernel(const float* __restrict__ out_b,
                             const int* __restrict__ context_input,
                             float* __restrict__ out) {
    extern __shared__ float copyv[];   // len floats
    const int half = blockIdx.x;
    const int b = blockIdx.y;
    const int tid = threadIdx.x;  // 256
    const int base = half ? VHALF : 0;
    const int len = half ? (VEXT - VHALF) : VHALF;

    for (int v = tid; v < len; v += 256) copyv[v] = 0.0f;
    __syncthreads();

    const float pg = g_pgen[b];
    if (tid < TC) {
        int idx = context_input[(size_t)b * TC + tid];
        if (idx >= base && idx < base + len) {
            float w = (1.0f - pg) * g_scores[1][b][tid];
            atomicAdd(&copyv[idx - base], w);
        }
    }
    __syncthreads();

    const float M = g_stats[b * 2 + 0];
    const float scale = g_stats[b * 2 + 1];
    const float* lg = g_logits + (size_t)b * LPAD;
    float* row = out + (size_t)b * VEXT;

    const int vend = (base + len < VV) ? (base + len) : VV;
    for (int v = base + tid; v < vend; v += 256) {
        float p = __expf(lg[v] + out_b[v] - M) * scale + copyv[v - base];
        row[v] = __logf(fmaxf(p, 1e-10f));
    }
    // OOV tail (only in half 1)
    for (int v = (VV > base ? VV : base) + tid; v < base + len; v += 256)
        row[v] = __logf(fmaxf(copyv[v - base], 1e-10f));
}

// ---------------- launcher ----------------
extern "C" void kernel_launch(void* const* d_in, const int* in_sizes, int n_in,
                              void* d_out, int out_size) {
    const int*   input    = (const int*)  d_in[0];
    const float* h0       = (const float*)d_in[1];
    const float* c0       = (const float*)d_in[2];
    const float* enc      = (const float*)d_in[3];
    const float* cenc     = (const float*)d_in[4];
    const int*   ctx_in   = (const int*)  d_in[5];
    const float* embedding= (const float*)d_in[6];
    const float* W_ih     = (const float*)d_in[7];
    const float* W_hh     = (const float*)d_in[8];
    const float* b_ih     = (const float*)d_in[9];
    const float* b_hh     = (const float*)d_in[10];
    const float* attn_W   = (const float*)d_in[11];
    const float* attn_b   = (const float*)d_in[12];
    const float* cattn_W  = (const float*)d_in[13];
    const float* cattn_b  = (const float*)d_in[14];
    const float* gen_W    = (const float*)d_in[15];
    const float* gen_b    = (const float*)d_in[16];
    const float* sig_b    = (const float*)d_in[17];
    const float* out_W    = (const float*)d_in[18];
    const float* out_b    = (const float*)d_in[19];

    float* out = (float*)d_out;
    float* logp   = out;
    float* h1_out = out + (size_t)BB * VEXT;
    float* c1_out = h1_out + (size_t)BB * HH;

    float* d_gates;  cudaGetSymbolAddress((void**)&d_gates,  g_gates);
    float* d_dec2;   cudaGetSymbolAddress((void**)&d_dec2,   g_dec2);
    float* d_logits; cudaGetSymbolAddress((void**)&d_logits, g_logits);

    const int SMEM128 = NSTG * (128 + 128) * ASTR * 4;   // 110592
    const int SMEM64  = NSTG * (128 + 64)  * ASTR * 4;   // 82944
    const int SMEM_WRITE = (VEXT - VHALF + 32) * 4;      // 100232
    cudaFuncSetAttribute(gemm_tc<128>,
        cudaFuncAttributeMaxDynamicSharedMemorySize, SMEM128);
    cudaFuncSetAttribute(gemm_tc<64>,
        cudaFuncAttributeMaxDynamicSharedMemorySize, SMEM64);
    cudaFuncSetAttribute(write_kernel,
        cudaFuncAttributeMaxDynamicSharedMemorySize, SMEM_WRITE);

    // 1) gates = [emb | h0] @ [W_ih | W_hh]^T   (K=768, K1=256, emb gathered)
    gemm_tc<64><<<H4 / 64, 256, SMEM64>>>(
        embedding, EE, h0, HH, input,
        W_ih, EE, W_hh, HH, EE,
        nullptr, 0, 0,
        d_gates, H4, H4, EE + HH);

    // 2) LSTM pointwise -> h1, c1 (into d_out tail)
    lstm_kernel<<<(BB * HH + 255) / 256, 256>>>(c0, b_ih, b_hh, h1_out, c1_out);

    // 3) [dec | cdec] = h1 @ [attn_W ; cattn_W]^T   (N=1024, N-split at 512)
    gemm_tc<64><<<1024 / 64, 256, SMEM64>>>(
        h1_out, HH, h1_out, HH, nullptr,
        attn_W, HH, attn_W, HH, HH,
        cattn_W, HH, HH,
        d_dec2, 1024, 1024, HH);

    // 4) BIG: logits = h1 @ out_W^T  (ncu slot)
    gemm_tc<128><<<LPAD / 128, 256, SMEM128>>>(
        h1_out, HH, h1_out, HH, nullptr,
        out_W, HH, out_W, HH, HH,
        nullptr, 0, 0,
        d_logits, LPAD, VV, HH);

    // 5) attention scores (both attns)
    scores_kernel<<<dim3(8, BB, 2), 128>>>(enc, cenc, attn_b, cattn_b);

    // 6) score softmax (both attns)
    score_softmax_kernel<<<dim3(BB, 2), 256>>>();

    // 7) contexts (both attns)
    ctx_kernel<<<dim3(4, BB, 2), 128>>>(enc, cenc);

    // 8) p_gen
    pgen_kernel<<<BB, 256>>>(h1_out, embedding, input, gen_W, gen_b, sig_b, ctx_in);

    // 9) softmax stats per row
    stats_kernel<<<BB, 512>>>(out_b);

    // 10) fused prob + copy-scatter + log, V-range split
    write_kernel<<<dim3(2, BB), 256, SMEM_WRITE>>>(out_b, ctx_in, logp);
}

// round 9
// speedup vs baseline: 1.5190x; 1.3268x over previous
#include <cuda_runtime.h>
#include <cuda_fp16.h>
#include <mma.h>
#include <math.h>
#include <cstdint>

using namespace nvcuda;

// ---------------- problem constants ----------------
#define BB   128
#define TT   256
#define TC   200
#define EE   256
#define HH   512
#define H4   2048
#define VV   50000
#define MAX_OOV 50
#define VEXT 50050
#define LPAD 50176   // padded logits row stride
#define VHALF 25024  // V-range split for write_kernel

#define ASTR 36      // wmma tf32 smem row stride in floats
#define NSTG 3       // tf32 gemm cp.async stages

// ---------------- scratch (device globals; no allocation) ----------------
__device__ float g_gates[BB * H4];
__device__ float g_dec2[BB * 1024];        // [dec | cdec] per row
__device__ float g_context[BB * HH];
__device__ float g_cctx[BB * HH];
__device__ float g_scores[2][BB][TT];
__device__ float g_pgen[BB];
__device__ float g_stats[BB * 2];          // {M, pgen/S} per row
__device__ float g_logits[BB * LPAD];

__device__ __forceinline__ float sigmoidf_(float x) {
    return 1.0f / (1.0f + __expf(-x));
}

// ---------------- cp.async helpers (tf32 gemm only) ----------------
__device__ __forceinline__ void cp_async16(uint32_t dst, const void* src) {
    asm volatile("cp.async.cg.shared.global [%0], [%1], 16;\n" :: "r"(dst), "l"(src));
}
__device__ __forceinline__ void cp_commit() {
    asm volatile("cp.async.commit_group;\n" ::);
}
template <int N>
__device__ __forceinline__ void cp_wait() {
    asm volatile("cp.async.wait_group %0;\n" :: "n"(N));
}

// block reduce: op 0 = max, 1 = sum (blockDim <= 1024)
__device__ __forceinline__ float block_reduce(float v, float* red, int op) {
    int lane = threadIdx.x & 31, warp = threadIdx.x >> 5;
    #pragma unroll
    for (int o = 16; o > 0; o >>= 1) {
        float u = __shfl_xor_sync(0xffffffffu, v, o);
        v = op ? (v + u) : fmaxf(v, u);
    }
    if (lane == 0) red[warp] = v;
    __syncthreads();
    int nw = (blockDim.x + 31) >> 5;
    if (warp == 0) {
        v = (lane < nw) ? red[lane] : (op ? 0.0f : -INFINITY);
        #pragma unroll
        for (int o = 16; o > 0; o >>= 1) {
            float u = __shfl_xor_sync(0xffffffffu, v, o);
            v = op ? (v + u) : fmaxf(v, u);
        }
        if (lane == 0) red[0] = v;
    }
    __syncthreads();
    float r = red[0];
    __syncthreads();
    return r;
}

// ============================================================================
// fp16 wmma GEMM: logits[128, n0:n0+128] = h1[128,512] @ out_W[n,512]^T
// 256 threads (8 warps, 2x4), warp tile 64x32, smem double buffer with
// register prefetch + on-the-fly fp32->fp16 conversion.
// fp16 mantissa == tf32 mantissa; operands are O(1)/O(0.02) so precision
// matches the tf32 path. Accumulation in fp32.
// ============================================================================
__global__ void __launch_bounds__(256)
logits_fp16(const float* __restrict__ A,   // h1 [128,512]
            const float* __restrict__ W,   // out_W [VV,512]
            float* __restrict__ C) {       // g_logits [128, LPAD]
    __shared__ __half As[2][128][40];      // 32 k + 8 pad halves
    __shared__ __half Ws[2][128][40];

    const int tid = threadIdx.x;
    const int wid = tid >> 5;
    const int warp_m = wid >> 2;           // 0..1 -> 64-row slab
    const int warp_n = wid & 3;            // 0..3 -> 32-col slab
    const int n0 = blockIdx.x * 128;
    const int KT = 16;                     // 512 / 32

    float4 ra[4], rw[4];

    auto ldg_stage = [&](int kt) {
        #pragma unroll
        for (int r = 0; r < 4; r++) {
            int f = tid + r * 256;
            int row = f >> 3, q = f & 7;
            ra[r] = *reinterpret_cast<const float4*>(
                A + (size_t)row * HH + kt * 32 + q * 4);
            int nr = n0 + row;
            if (nr >= VV) nr = VV - 1;
            rw[r] = *reinterpret_cast<const float4*>(
                W + (size_t)nr * HH + kt * 32 + q * 4);
        }
    };
    auto sts_stage = [&](int s) {
        #pragma unroll
        for (int r = 0; r < 4; r++) {
            int f = tid + r * 256;
            int row = f >> 3, q = f & 7;
            *reinterpret_cast<__half2*>(&As[s][row][q * 4]) =
                __floats2half2_rn(ra[r].x, ra[r].y);
            *reinterpret_cast<__half2*>(&As[s][row][q * 4 + 2]) =
                __floats2half2_rn(ra[r].z, ra[r].w);
            *reinterpret_cast<__half2*>(&Ws[s][row][q * 4]) =
                __floats2half2_rn(rw[r].x, rw[r].y);
            *reinterpret_cast<__half2*>(&Ws[s][row][q * 4 + 2]) =
                __floats2half2_rn(rw[r].z, rw[r].w);
        }
    };

    wmma::fragment<wmma::accumulator, 16, 16, 16, float> c[4][2];
    #pragma unroll
    for (int i = 0; i < 4; i++)
        #pragma unroll
        for (int j = 0; j < 2; j++) wmma::fill_fragment(c[i][j], 0.0f);

    ldg_stage(0);
    sts_stage(0);
    ldg_stage(1);
    __syncthreads();

    for (int kt = 0; kt < KT; kt++) {
        if (kt + 1 < KT) sts_stage((kt + 1) & 1);  // other buffer: safe
        if (kt + 2 < KT) ldg_stage(kt + 2);        // LDG hidden behind compute

        const int s = kt & 1;
        #pragma unroll
        for (int k16 = 0; k16 < 32; k16 += 16) {
            wmma::fragment<wmma::matrix_a, 16, 16, 16, __half,
                           wmma::row_major> a[4];
            wmma::fragment<wmma::matrix_b, 16, 16, 16, __half,
                           wmma::col_major> b[2];
            #pragma unroll
            for (int mi = 0; mi < 4; mi++)
                wmma::load_matrix_sync(a[mi],
                    &As[s][warp_m * 64 + mi * 16][k16], 40);
            #pragma unroll
            for (int ni = 0; ni < 2; ni++)
                wmma::load_matrix_sync(b[ni],
                    &Ws[s][warp_n * 32 + ni * 16][k16], 40);
            #pragma unroll
            for (int mi = 0; mi < 4; mi++)
                #pragma unroll
                for (int ni = 0; ni < 2; ni++)
                    wmma::mma_sync(c[mi][ni], a[mi], b[ni], c[mi][ni]);
        }
        __syncthreads();
    }

    #pragma unroll
    for (int mi = 0; mi < 4; mi++)
        #pragma unroll
        for (int ni = 0; ni < 2; ni++)
            wmma::store_matrix_sync(
                &C[(size_t)(warp_m * 64 + mi * 16) * LPAD + n0 + warp_n * 32 + ni * 16],
                c[mi][ni], LPAD, wmma::mem_row_major);
}

// ============================================================================
// wmma tf32 GEMM (small GEMMs): C[128, N] = A[128, K] * W[N, K]^T
// ============================================================================
template <int BN>
__global__ void __launch_bounds__(256, 2)
gemm_tc(const float* __restrict__ A1, int lda1,
        const float* __restrict__ A2, int lda2,
        const int* __restrict__ gather_idx,
        const float* __restrict__ W1, int ldw1,
        const float* __restrict__ W2, int ldw2, int K1,
        const float* __restrict__ Wn2, int ldwn2, int Nsplit,
        float* __restrict__ C, int ldc,
        int N, int K) {
    extern __shared__ float smem[];
    float* As = smem;
    float* Ws = smem + NSTG * 128 * ASTR;

    const int tid = threadIdx.x;
    const int wid = tid >> 5;
    const int warp_m = wid >> 1;
    const int warp_n = wid & 1;
    const int n0 = blockIdx.x * BN;
    constexpr int WN = BN / 2;
    constexpr int NI = WN / 16;
    const int KT = K >> 5;

    const uint32_t as_base = (uint32_t)__cvta_generic_to_shared(As);
    const uint32_t ws_base = (uint32_t)__cvta_generic_to_shared(Ws);

    auto issue_stage = [&](int kt, int s) {
        const int kk = kt << 5;
        #pragma unroll
        for (int r = 0; r < 4; r++) {
            int f = tid + r * 256;
            int row = f >> 3, kq = f & 7;
            int k = kk + kq * 4;
            const float* src;
            if (k < K1) {
                int arow = gather_idx ? gather_idx[row] : row;
                src = A1 + (size_t)arow * lda1 + k;
            } else {
                src = A2 + (size_t)row * lda2 + (k - K1);
            }
            cp_async16(as_base + (uint32_t)((s * 128 + row) * ASTR + kq * 4) * 4, src);
        }
        #pragma unroll
        for (int r = 0; r < BN / 32; r++) {
            int f = tid + r * 256;
            int row = f >> 3, kq = f & 7;
            int k = kk + kq * 4;
            int nr = n0 + row;
            if (nr >= N) nr = N - 1;
            const float* src;
            if (k < K1) {
                if (Wn2 && nr >= Nsplit)
                    src = Wn2 + (size_t)(nr - Nsplit) * ldwn2 + k;
                else
                    src = W1 + (size_t)nr * ldw1 + k;
            } else {
                src = W2 + (size_t)nr * ldw2 + (k - K1);
            }
            cp_async16(ws_base + (uint32_t)((s * BN + row) * ASTR + kq * 4) * 4, src);
        }
        cp_commit();
    };

    wmma::fragment<wmma::accumulator, 16, 16, 8, float> c[2][NI];
    #pragma unroll
    for (int i = 0; i < 2; i++)
        #pragma unroll
        for (int j = 0; j < NI; j++) wmma::fill_fragment(c[i][j], 0.0f);

    issue_stage(0, 0);
    if (KT > 1) issue_stage(1, 1);

    for (int kt = 0; kt < KT; kt++) {
        if (kt + 2 < KT) {
            issue_stage(kt + 2, (kt + 2) % NSTG);
            cp_wait<2>();
        } else if (kt + 1 < KT) {
            cp_wait<1>();
        } else {
            cp_wait<0>();
        }
        __syncthreads();

        const int s = kt % NSTG;
        const float* as = As + (size_t)s * 128 * ASTR;
        const float* ws = Ws + (size_t)s * BN * ASTR;

        #pragma unroll
        for (int k8 = 0; k8 < 32; k8 += 8) {
            wmma::fragment<wmma::matrix_a, 16, 16, 8, wmma::precision::tf32,
                           wmma::row_major> a[2];
            wmma::fragment<wmma::matrix_b, 16, 16, 8, wmma::precision::tf32,
                           wmma::col_major> b[NI];
            #pragma unroll
            for (int mi = 0; mi < 2; mi++)
                wmma::load_matrix_sync(a[mi],
                    as + (warp_m * 32 + mi * 16) * ASTR + k8, ASTR);
            #pragma unroll
            for (int ni = 0; ni < NI; ni++)
                wmma::load_matrix_sync(b[ni],
                    ws + (warp_n * WN + ni * 16) * ASTR + k8, ASTR);
            #pragma unroll
            for (int mi = 0; mi < 2; mi++)
                #pragma unroll
                for (int ni = 0; ni < NI; ni++)
                    wmma::mma_sync(c[mi][ni], a[mi], b[ni], c[mi][ni]);
        }
        __syncthreads();
    }

    #pragma unroll
    for (int mi = 0; mi < 2; mi++)
        #pragma unroll
        for (int ni = 0; ni < NI; ni++)
            wmma::store_matrix_sync(
                &C[(size_t)(warp_m * 32 + mi * 16) * ldc + n0 + warp_n * WN + ni * 16],
                c[mi][ni], ldc, wmma::mem_row_major);
}

// ---------------- LSTM pointwise ----------------
__global__ void lstm_kernel(const float* __restrict__ c0,
                            const float* __restrict__ b_ih,
                            const float* __restrict__ b_hh,
                            float* __restrict__ h1_out,
                            float* __restrict__ c1_out) {
    int i = blockIdx.x * blockDim.x + threadIdx.x;
    if (i >= BB * HH) return;
    int b = i / HH, h = i % HH;
    const float* g = g_gates + (size_t)b * H4;
    float gi = g[h]          + b_ih[h]          + b_hh[h];
    float gf = g[HH + h]     + b_ih[HH + h]     + b_hh[HH + h];
    float gg = g[2 * HH + h] + b_ih[2 * HH + h] + b_hh[2 * HH + h];
    float go = g[3 * HH + h] + b_ih[3 * HH + h] + b_hh[3 * HH + h];
    float c = sigmoidf_(gf) * c0[i] + sigmoidf_(gi) * tanhf(gg);
    float hh = sigmoidf_(go) * tanhf(c);
    c1_out[i] = c;
    h1_out[i] = hh;
}

// ---------------- attention scores (raw): grid (8, B, 2), 128 threads ----------------
__global__ void scores_kernel(const float* __restrict__ enc,
                              const float* __restrict__ cenc,
                              const float* __restrict__ attn_b,
                              const float* __restrict__ cattn_b) {
    const int aid = blockIdx.z;
    const int b = blockIdx.y;
    const int t0 = blockIdx.x * 32;
    const int T = aid ? TC : TT;
    if (t0 >= T) return;

    __shared__ float sdec[HH];
    const int tid = threadIdx.x;
    {
        const float* dec = g_dec2 + (size_t)b * 1024 + aid * HH;
        const float* bias = aid ? cattn_b : attn_b;
        #pragma unroll
        for (int i = 0; i < 4; i++)
            sdec[tid + i * 128] = dec[tid + i * 128] + bias[tid + i * 128];
    }
    __syncthreads();

    const float* eb = (aid ? cenc : enc) + (size_t)b * T * HH;
    const int warp = tid >> 5, lane = tid & 31;

    #pragma unroll
    for (int j = 0; j < 8; j++) {
        int t = t0 + warp * 8 + j;
        if (t < T) {
            const float4* row = reinterpret_cast<const float4*>(eb + (size_t)t * HH);
            float s = 0.0f;
            #pragma unroll
            for (int q = 0; q < 4; q++) {
                int f4 = lane + 32 * q;
                float4 v = row[f4];
                s += v.x * sdec[f4 * 4 + 0] + v.y * sdec[f4 * 4 + 1] +
                     v.z * sdec[f4 * 4 + 2] + v.w * sdec[f4 * 4 + 3];
            }
            #pragma unroll
            for (int o = 16; o > 0; o >>= 1) s += __shfl_xor_sync(0xffffffffu, s, o);
            if (lane == 0) g_scores[aid][b][t] = s;
        }
    }
}

// ---------------- per-row score softmax: grid (B, 2), 256 threads ----------------
__global__ void score_softmax_kernel() {
    const int b = blockIdx.x;
    const int aid = blockIdx.y;
    const int T = aid ? TC : TT;
    const int tid = threadIdx.x;
    __shared__ float red[32];
    float* sc = g_scores[aid][b];

    float v = (tid < T) ? sc[tid] : -INFINITY;
    float m = block_reduce(v, red, 0);
    float e = (tid < T) ? __expf(v - m) : 0.0f;
    float s = block_reduce(e, red, 1);
    if (tid < T) sc[tid] = e / s;
}

// ---------------- attention context: grid (4, B, 2), 128 threads ----------------
__global__ void ctx_kernel(const float* __restrict__ enc,
                           const float* __restrict__ cenc) {
    const int hc = blockIdx.x;
    const int b = blockIdx.y;
    const int aid = blockIdx.z;
    const int T = aid ? TC : TT;
    const int tid = threadIdx.x;

    __shared__ float sw[TT];
    for (int t = tid; t < T; t += 128) sw[t] = g_scores[aid][b][t];
    __syncthreads();

    const float* eb = (aid ? cenc : enc) + (size_t)b * T * HH + hc * 128 + tid;
    float acc = 0.0f;
    int t = 0;
    for (; t + 4 <= T; t += 4) {
        float x0 = eb[(size_t)(t + 0) * HH];
        float x1 = eb[(size_t)(t + 1) * HH];
        float x2 = eb[(size_t)(t + 2) * HH];
        float x3 = eb[(size_t)(t + 3) * HH];
        acc += sw[t] * x0 + sw[t + 1] * x1 + sw[t + 2] * x2 + sw[t + 3] * x3;
    }
    for (; t < T; t++) acc += sw[t] * eb[(size_t)t * HH];

    float* dst = aid ? g_cctx : g_context;
    dst[(size_t)b * HH + hc * 128 + tid] = acc;
}

// ---------------- p_gen ----------------
__global__ void pgen_kernel(const float* __restrict__ h1,
                            const float* __restrict__ embedding,
                            const int* __restrict__ input,
                            const float* __restrict__ gen_W,
                            const float* __restrict__ gen_b,
                            const float* __restrict__ sig_b,
                            const int* __restrict__ context_input) {
    __shared__ float red[32];
    int b = blockIdx.x;
    int tid = threadIdx.x;
    float s = 0.0f;
    for (int k = tid; k < HH; k += 256) s += g_context[b * HH + k] * gen_W[k];
    for (int k = tid; k < HH; k += 256) s += g_cctx[b * HH + k] * gen_W[HH + k];
    for (int k = tid; k < HH; k += 256) s += h1[b * HH + k] * gen_W[2 * HH + k];
    {
        const float* emb = embedding + (size_t)input[b] * EE;
        for (int k = tid; k < EE; k += 256) s += emb[k] * gen_W[3 * HH + k];
    }
    s = block_reduce(s, red, 1);

    float cnt = 0.0f;
    for (int t = tid; t < TC; t += 256)
        cnt += (context_input[(size_t)b * TC + t] > 0) ? 1.0f : 0.0f;
    cnt = block_reduce(cnt, red, 1);

    if (tid == 0) {
        float p = sigmoidf_(s + gen_b[0] + sig_b[0]);
        if (cnt == 0.0f) p = 1.0f;
        g_pgen[b] = p;
    }
}

// ---------------- stats: per-row softmax max + scale: grid (B), 512 thr ----------------
__global__ void stats_kernel(const float* __restrict__ out_b) {
    __shared__ float red[32];
    const int b = blockIdx.x;
    const int tid = threadIdx.x;
    const float* lg = g_logits + (size_t)b * LPAD;

    float m = -INFINITY, s = 0.0f;
    for (int v = tid; v < VV; v += 512) {
        float x = lg[v] + out_b[v];
        if (x > m) {
            s = s * __expf(m - x) + 1.0f;
            m = x;
        } else {
            s += __expf(x - m);
        }
    }
    float M = block_reduce(m, red, 0);
    s = (m == -INFINITY) ? 0.0f : s * __expf(m - M);
    float S = block_reduce(s, red, 1);

    if (tid == 0) {
        g_stats[b * 2 + 0] = M;
        g_stats[b * 2 + 1] = g_pgen[b] / S;
    }
}

// ---------------- write: half-V-range prob + copy + log: grid (2, B), 256 thr ----------------
__global__ void write_kernel(const float* __restrict__ out_b,
                             const int* __restrict__ context_input,
                             float* __restrict__ out) {
    extern __shared__ float copyv[];
    const int half = blockIdx.x;
    const int b = blockIdx.y;
    const int tid = threadIdx.x;
    const int base = half ? VHALF : 0;
    const int len = half ? (VEXT - VHALF) : VHALF;

    for (int v = tid; v < len; v += 256) copyv[v] = 0.0f;
    __syncthreads();

    const float pg = g_pgen[b];
    if (tid < TC) {
        int idx = context_input[(size_t)b * TC + tid];
        if (idx >= base && idx < base + len) {
            float w = (1.0f - pg) * g_scores[1][b][tid];
            atomicAdd(&copyv[idx - base], w);
        }
    }
    __syncthreads();

    const float M = g_stats[b * 2 + 0];
    const float scale = g_stats[b * 2 + 1];
    const float* lg = g_logits + (size_t)b * LPAD;
    float* row = out + (size_t)b * VEXT;

    const int vend = (base + len < VV) ? (base + len) : VV;
    for (int v = base + tid; v < vend; v += 256) {
        float p = __expf(lg[v] + out_b[v] - M) * scale + copyv[v - base];
        row[v] = __logf(fmaxf(p, 1e-10f));
    }
    for (int v = (VV > base ? VV : base) + tid; v < base + len; v += 256)
        row[v] = __logf(fmaxf(copyv[v - base], 1e-10f));
}

// ---------------- launcher ----------------
extern "C" void kernel_launch(void* const* d_in, const int* in_sizes, int n_in,
                              void* d_out, int out_size) {
    const int*   input    = (const int*)  d_in[0];
    const float* h0       = (const float*)d_in[1];
    const float* c0       = (const float*)d_in[2];
    const float* enc      = (const float*)d_in[3];
    const float* cenc     = (const float*)d_in[4];
    const int*   ctx_in   = (const int*)  d_in[5];
    const float* embedding= (const float*)d_in[6];
    const float* W_ih     = (const float*)d_in[7];
    const float* W_hh     = (const float*)d_in[8];
    const float* b_ih     = (const float*)d_in[9];
    const float* b_hh     = (const float*)d_in[10];
    const float* attn_W   = (const float*)d_in[11];
    const float* attn_b   = (const float*)d_in[12];
    const float* cattn_W  = (const float*)d_in[13];
    const float* cattn_b  = (const float*)d_in[14];
    const float* gen_W    = (const float*)d_in[15];
    const float* gen_b    = (const float*)d_in[16];
    const float* sig_b    = (const float*)d_in[17];
    const float* out_W    = (const float*)d_in[18];
    const float* out_b    = (const float*)d_in[19];

    float* out = (float*)d_out;
    float* logp   = out;
    float* h1_out = out + (size_t)BB * VEXT;
    float* c1_out = h1_out + (size_t)BB * HH;

    float* d_gates;  cudaGetSymbolAddress((void**)&d_gates,  g_gates);
    float* d_dec2;   cudaGetSymbolAddress((void**)&d_dec2,   g_dec2);
    float* d_logits; cudaGetSymbolAddress((void**)&d_logits, g_logits);

    const int SMEM64  = NSTG * (128 + 64)  * ASTR * 4;     // 82944
    const int SMEM_WRITE = (VEXT - VHALF + 32) * 4;        // 100232
    cudaFuncSetAttribute(gemm_tc<64>,
        cudaFuncAttributeMaxDynamicSharedMemorySize, SMEM64);
    cudaFuncSetAttribute(write_kernel,
        cudaFuncAttributeMaxDynamicSharedMemorySize, SMEM_WRITE);

    // 1) gates = [emb | h0] @ [W_ih | W_hh]^T   (K=768, K1=256, emb gathered)
    gemm_tc<64><<<H4 / 64, 256, SMEM64>>>(
        embedding, EE, h0, HH, input,
        W_ih, EE, W_hh, HH, EE,
        nullptr, 0, 0,
        d_gates, H4, H4, EE + HH);

    // 2) LSTM pointwise -> h1, c1 (into d_out tail)
    lstm_kernel<<<(BB * HH + 255) / 256, 256>>>(c0, b_ih, b_hh, h1_out, c1_out);

    // 3) [dec | cdec] = h1 @ [attn_W ; cattn_W]^T
    gemm_tc<64><<<1024 / 64, 256, SMEM64>>>(
        h1_out, HH, h1_out, HH, nullptr,
        attn_W, HH, attn_W, HH, HH,
        cattn_W, HH, HH,
        d_dec2, 1024, 1024, HH);

    // 4) attention scores (both attns) [ncu slot this round]
    scores_kernel<<<dim3(8, BB, 2), 128>>>(enc, cenc, attn_b, cattn_b);

    // 5) score softmax (both attns)
    score_softmax_kernel<<<dim3(BB, 2), 256>>>();

    // 6) contexts (both attns)
    ctx_kernel<<<dim3(4, BB, 2), 128>>>(enc, cenc);

    // 7) BIG: logits = h1 @ out_W^T via fp16 wmma
    logits_fp16<<<LPAD / 128, 256>>>(h1_out, out_W, d_logits);

    // 8) p_gen
    pgen_kernel<<<BB, 256>>>(h1_out, embedding, input, gen_W, gen_b, sig_b, ctx_in);

    // 9) softmax stats per row
    stats_kernel<<<BB, 512>>>(out_b);

    // 10) fused prob + copy-scatter + log, V-range split
    write_kernel<<<dim3(2, BB), 256, SMEM_WRITE>>>(out_b, ctx_in, logp);
}

// round 10
// speedup vs baseline: 1.8360x; 1.2087x over previous
#include <cuda_runtime.h>
#include <cuda_fp16.h>
#include <mma.h>
#include <math.h>
#include <cstdint>

using namespace nvcuda;

// ---------------- problem constants ----------------
#define BB   128
#define TT   256
#define TC   200
#define EE   256
#define HH   512
#define H4   2048
#define VV   50000
#define MAX_OOV 50
#define VEXT 50050
#define LPAD 50176   // padded logits row stride

#define QSTAT 12500  // stats partial range (VV/4)
#define QWR   12513  // write quarter range (ceil VEXT/4)

#define ASTR 36      // tf32 gemm smem row stride (floats)
#define NSTG 3       // tf32 gemm cp.async stages

#define NLOGIT (LPAD / 128)        // 392 logits blocks
#define NDEC   8                   // dec2 blocks (N=1024)
#define NSCORE 2048                // scores blocks (8 x 128 x 2)

// ---------------- scratch (device globals; no allocation) ----------------
__device__ float g_gates[BB * H4];
__device__ float g_dec2[BB * 1024];        // [dec | cdec] per row
__device__ float g_context[BB * HH];
__device__ float g_cctx[BB * HH];
__device__ float g_scores[2][BB][TT];      // raw scores
__device__ float g_nscores[BB][TT];        // normalized cscores (attn 1)
__device__ float g_pgen[BB];
__device__ float g_part[BB][4][2];         // per-quarter online {m, s}
__device__ float g_logits[BB * LPAD];

__device__ __forceinline__ float sigmoidf_(float x) {
    return 1.0f / (1.0f + __expf(-x));
}

// ---------------- cp.async helpers (tf32 gemm only) ----------------
__device__ __forceinline__ void cp_async16(uint32_t dst, const void* src) {
    asm volatile("cp.async.cg.shared.global [%0], [%1], 16;\n" :: "r"(dst), "l"(src));
}
__device__ __forceinline__ void cp_commit() {
    asm volatile("cp.async.commit_group;\n" ::);
}
template <int N>
__device__ __forceinline__ void cp_wait() {
    asm volatile("cp.async.wait_group %0;\n" :: "n"(N));
}

// block reduce: op 0 = max, 1 = sum (blockDim <= 1024)
__device__ __forceinline__ float block_reduce(float v, float* red, int op) {
    int lane = threadIdx.x & 31, warp = threadIdx.x >> 5;
    #pragma unroll
    for (int o = 16; o > 0; o >>= 1) {
        float u = __shfl_xor_sync(0xffffffffu, v, o);
        v = op ? (v + u) : fmaxf(v, u);
    }
    if (lane == 0) red[warp] = v;
    __syncthreads();
    int nw = (blockDim.x + 31) >> 5;
    if (warp == 0) {
        v = (lane < nw) ? red[lane] : (op ? 0.0f : -INFINITY);
        #pragma unroll
        for (int o = 16; o > 0; o >>= 1) {
            float u = __shfl_xor_sync(0xffffffffu, v, o);
            v = op ? (v + u) : fmaxf(v, u);
        }
        if (lane == 0) red[0] = v;
    }
    __syncthreads();
    float r = red[0];
    __syncthreads();
    return r;
}

// ============================================================================
// Mega fp16 wmma GEMM (one launch):
//   blocks [0, NLOGIT):        logits[128, n0:n0+128] = h1 @ out_W^T
//   blocks [NLOGIT, +NDEC):    dec2  [128, n0:n0+128] = h1 @ [attn_W;cattn_W]^T
// 256 threads (8 warps, 2x4), warp tile 64x32, reg-prefetch double buffer.
// ============================================================================
__global__ void __launch_bounds__(256)
mega_fp16(const float* __restrict__ A,        // h1 [128,512]
          const float* __restrict__ Wout,     // [VV,512]
          const float* __restrict__ Wattn,    // [512,512]
          const float* __restrict__ Wcattn,   // [512,512]
          float* __restrict__ Clog,           // g_logits
          float* __restrict__ Cdec) {         // g_dec2
    __shared__ __half As[2][128][40];
    __shared__ __half Ws[2][128][40];

    const int tid = threadIdx.x;
    const int wid = tid >> 5;
    const int warp_m = wid >> 2;
    const int warp_n = wid & 3;
    const bool is_dec = (blockIdx.x >= NLOGIT);
    const int n0 = (is_dec ? (int)blockIdx.x - NLOGIT : (int)blockIdx.x) * 128;
    float* C = is_dec ? Cdec : Clog;
    const int ldc = is_dec ? 1024 : LPAD;
    const int KT = 16;

    float4 ra[4], rw[4];

    auto wrow = [&](int nr) -> const float* {
        if (is_dec)
            return (nr < 512) ? Wattn + (size_t)nr * HH
                              : Wcattn + (size_t)(nr - 512) * HH;
        if (nr >= VV) nr = VV - 1;
        return Wout + (size_t)nr * HH;
    };

    auto ldg_stage = [&](int kt) {
        #pragma unroll
        for (int r = 0; r < 4; r++) {
            int f = tid + r * 256;
            int row = f >> 3, q = f & 7;
            ra[r] = *reinterpret_cast<const float4*>(
                A + (size_t)row * HH + kt * 32 + q * 4);
            rw[r] = *reinterpret_cast<const float4*>(
                wrow(n0 + row) + kt * 32 + q * 4);
        }
    };
    auto sts_stage = [&](int s) {
        #pragma unroll
        for (int r = 0; r < 4; r++) {
            int f = tid + r * 256;
            int row = f >> 3, q = f & 7;
            *reinterpret_cast<__half2*>(&As[s][row][q * 4]) =
                __floats2half2_rn(ra[r].x, ra[r].y);
            *reinterpret_cast<__half2*>(&As[s][row][q * 4 + 2]) =
                __floats2half2_rn(ra[r].z, ra[r].w);
            *reinterpret_cast<__half2*>(&Ws[s][row][q * 4]) =
                __floats2half2_rn(rw[r].x, rw[r].y);
            *reinterpret_cast<__half2*>(&Ws[s][row][q * 4 + 2]) =
                __floats2half2_rn(rw[r].z, rw[r].w);
        }
    };

    wmma::fragment<wmma::accumulator, 16, 16, 16, float> c[4][2];
    #pragma unroll
    for (int i = 0; i < 4; i++)
        #pragma unroll
        for (int j = 0; j < 2; j++) wmma::fill_fragment(c[i][j], 0.0f);

    ldg_stage(0);
    sts_stage(0);
    ldg_stage(1);
    __syncthreads();

    for (int kt = 0; kt < KT; kt++) {
        if (kt + 1 < KT) sts_stage((kt + 1) & 1);
        if (kt + 2 < KT) ldg_stage(kt + 2);

        const int s = kt & 1;
        #pragma unroll
        for (int k16 = 0; k16 < 32; k16 += 16) {
            wmma::fragment<wmma::matrix_a, 16, 16, 16, __half,
                           wmma::row_major> a[4];
            wmma::fragment<wmma::matrix_b, 16, 16, 16, __half,
                           wmma::col_major> b[2];
            #pragma unroll
            for (int mi = 0; mi < 4; mi++)
                wmma::load_matrix_sync(a[mi],
                    &As[s][warp_m * 64 + mi * 16][k16], 40);
            #pragma unroll
            for (int ni = 0; ni < 2; ni++)
                wmma::load_matrix_sync(b[ni],
                    &Ws[s][warp_n * 32 + ni * 16][k16], 40);
            #pragma unroll
            for (int mi = 0; mi < 4; mi++)
                #pragma unroll
                for (int ni = 0; ni < 2; ni++)
                    wmma::mma_sync(c[mi][ni], a[mi], b[ni], c[mi][ni]);
        }
        __syncthreads();
    }

    #pragma unroll
    for (int mi = 0; mi < 4; mi++)
        #pragma unroll
        for (int ni = 0; ni < 2; ni++)
            wmma::store_matrix_sync(
                &C[(size_t)(warp_m * 64 + mi * 16) * ldc + n0 + warp_n * 32 + ni * 16],
                c[mi][ni], ldc, wmma::mem_row_major);
}

// ============================================================================
// wmma tf32 GEMM (gates): C[128, N] = A[128, K] * W[N, K]^T
// ============================================================================
template <int BN>
__global__ void __launch_bounds__(256, 2)
gemm_tc(const float* __restrict__ A1, int lda1,
        const float* __restrict__ A2, int lda2,
        const int* __restrict__ gather_idx,
        const float* __restrict__ W1, int ldw1,
        const float* __restrict__ W2, int ldw2, int K1,
        float* __restrict__ C, int ldc,
        int N, int K) {
    extern __shared__ float smem[];
    float* As = smem;
    float* Ws = smem + NSTG * 128 * ASTR;

    const int tid = threadIdx.x;
    const int wid = tid >> 5;
    const int warp_m = wid >> 1;
    const int warp_n = wid & 1;
    const int n0 = blockIdx.x * BN;
    constexpr int WN = BN / 2;
    constexpr int NI = WN / 16;
    const int KT = K >> 5;

    const uint32_t as_base = (uint32_t)__cvta_generic_to_shared(As);
    const uint32_t ws_base = (uint32_t)__cvta_generic_to_shared(Ws);

    auto issue_stage = [&](int kt, int s) {
        const int kk = kt << 5;
        #pragma unroll
        for (int r = 0; r < 4; r++) {
            int f = tid + r * 256;
            int row = f >> 3, kq = f & 7;
            int k = kk + kq * 4;
            const float* src;
            if (k < K1) {
                int arow = gather_idx ? gather_idx[row] : row;
                src = A1 + (size_t)arow * lda1 + k;
            } else {
                src = A2 + (size_t)row * lda2 + (k - K1);
            }
            cp_async16(as_base + (uint32_t)((s * 128 + row) * ASTR + kq * 4) * 4, src);
        }
        #pragma unroll
        for (int r = 0; r < BN / 32; r++) {
            int f = tid + r * 256;
            int row = f >> 3, kq = f & 7;
            int k = kk + kq * 4;
            int nr = n0 + row;
            if (nr >= N) nr = N - 1;
            const float* src = (k < K1)
                ? W1 + (size_t)nr * ldw1 + k
                : W2 + (size_t)nr * ldw2 + (k - K1);
            cp_async16(ws_base + (uint32_t)((s * BN + row) * ASTR + kq * 4) * 4, src);
        }
        cp_commit();
    };

    wmma::fragment<wmma::accumulator, 16, 16, 8, float> c[2][NI];
    #pragma unroll
    for (int i = 0; i < 2; i++)
        #pragma unroll
        for (int j = 0; j < NI; j++) wmma::fill_fragment(c[i][j], 0.0f);

    issue_stage(0, 0);
    if (KT > 1) issue_stage(1, 1);

    for (int kt = 0; kt < KT; kt++) {
        if (kt + 2 < KT) {
            issue_stage(kt + 2, (kt + 2) % NSTG);
            cp_wait<2>();
        } else if (kt + 1 < KT) {
            cp_wait<1>();
        } else {
            cp_wait<0>();
        }
        __syncthreads();

        const int s = kt % NSTG;
        const float* as = As + (size_t)s * 128 * ASTR;
        const float* ws = Ws + (size_t)s * BN * ASTR;

        #pragma unroll
        for (int k8 = 0; k8 < 32; k8 += 8) {
            wmma::fragment<wmma::matrix_a, 16, 16, 8, wmma::precision::tf32,
                           wmma::row_major> a[2];
            wmma::fragment<wmma::matrix_b, 16, 16, 8, wmma::precision::tf32,
                           wmma::col_major> b[NI];
            #pragma unroll
            for (int mi = 0; mi < 2; mi++)
                wmma::load_matrix_sync(a[mi],
                    as + (warp_m * 32 + mi * 16) * ASTR + k8, ASTR);
            #pragma unroll
            for (int ni = 0; ni < NI; ni++)
                wmma::load_matrix_sync(b[ni],
                    ws + (warp_n * WN + ni * 16) * ASTR + k8, ASTR);
            #pragma unroll
            for (int mi = 0; mi < 2; mi++)
                #pragma unroll
                for (int ni = 0; ni < NI; ni++)
                    wmma::mma_sync(c[mi][ni], a[mi], b[ni], c[mi][ni]);
        }
        __syncthreads();
    }

    #pragma unroll
    for (int mi = 0; mi < 2; mi++)
        #pragma unroll
        for (int ni = 0; ni < NI; ni++)
            wmma::store_matrix_sync(
                &C[(size_t)(warp_m * 32 + mi * 16) * ldc + n0 + warp_n * WN + ni * 16],
                c[mi][ni], ldc, wmma::mem_row_major);
}

// ---------------- LSTM pointwise ----------------
__global__ void lstm_kernel(const float* __restrict__ c0,
                            const float* __restrict__ b_ih,
                            const float* __restrict__ b_hh,
                            float* __restrict__ h1_out,
                            float* __restrict__ c1_out) {
    int i = blockIdx.x * blockDim.x + threadIdx.x;
    if (i >= BB * HH) return;
    int b = i / HH, h = i % HH;
    const float* g = g_gates + (size_t)b * H4;
    float gi = g[h]          + b_ih[h]          + b_hh[h];
    float gf = g[HH + h]     + b_ih[HH + h]     + b_hh[HH + h];
    float gg = g[2 * HH + h] + b_ih[2 * HH + h] + b_hh[2 * HH + h];
    float go = g[3 * HH + h] + b_ih[3 * HH + h] + b_hh[3 * HH + h];
    float c = sigmoidf_(gf) * c0[i] + sigmoidf_(gi) * tanhf(gg);
    float hh = sigmoidf_(go) * tanhf(c);
    c1_out[i] = c;
    h1_out[i] = hh;
}

// ============================================================================
// Merged: attention scores (blocks [0, NSCORE)) + stats partials (next 512).
// 256 threads everywhere.
// ============================================================================
__global__ void __launch_bounds__(256)
scores_stats(const float* __restrict__ enc,
             const float* __restrict__ cenc,
             const float* __restrict__ attn_b,
             const float* __restrict__ cattn_b,
             const float* __restrict__ out_b) {
    __shared__ float sred[HH];   // doubles as sdec / reduce scratch
    const int tid = threadIdx.x;

    if (blockIdx.x < NSCORE) {
        // ---- scores part: idx -> (t0, b, aid) ----
        const int idx = blockIdx.x;
        const int aid = idx >> 10;           // /1024
        const int b = (idx & 1023) >> 3;     // /8
        const int t0 = (idx & 7) * 32;
        const int T = aid ? TC : TT;
        if (t0 >= T) return;

        float* sdec = sred;
        {
            const float* dec = g_dec2 + (size_t)b * 1024 + aid * HH;
            const float* bias = aid ? cattn_b : attn_b;
            sdec[tid] = dec[tid] + bias[tid];
            sdec[tid + 256] = dec[tid + 256] + bias[tid + 256];
        }
        __syncthreads();

        const float* eb = (aid ? cenc : enc) + (size_t)b * T * HH;
        const int warp = tid >> 5, lane = tid & 31;

        #pragma unroll
        for (int j = 0; j < 4; j++) {
            int t = t0 + warp * 4 + j;
            if (t < T) {
                const float4* row = reinterpret_cast<const float4*>(eb + (size_t)t * HH);
                float s = 0.0f;
                #pragma unroll
                for (int q = 0; q < 4; q++) {
                    int f4 = lane + 32 * q;
                    float4 v = row[f4];
                    s += v.x * sdec[f4 * 4 + 0] + v.y * sdec[f4 * 4 + 1] +
                         v.z * sdec[f4 * 4 + 2] + v.w * sdec[f4 * 4 + 3];
                }
                #pragma unroll
                for (int o = 16; o > 0; o >>= 1)
                    s += __shfl_xor_sync(0xffffffffu, s, o);
                if (lane == 0) g_scores[aid][b][t] = s;
            }
        }
    } else {
        // ---- stats partial: quarter-range online (m, s) over logits+bias ----
        const int idx = blockIdx.x - NSCORE;
        const int q = idx & 3;
        const int b = idx >> 2;
        const int v0 = q * QSTAT;
        const int v1 = (q == 3) ? VV : v0 + QSTAT;
        const float* lg = g_logits + (size_t)b * LPAD;

        float m = -INFINITY, s = 0.0f;
        for (int v = v0 + tid; v < v1; v += 256) {
            float x = lg[v] + out_b[v];
            if (x > m) {
                s = s * __expf(m - x) + 1.0f;
                m = x;
            } else {
                s += __expf(x - m);
            }
        }
        float M = block_reduce(m, sred, 0);
        s = (m == -INFINITY) ? 0.0f : s * __expf(m - M);
        float S = block_reduce(s, sred, 1);
        if (tid == 0) {
            g_part[b][q][0] = M;
            g_part[b][q][1] = S;
        }
    }
}

// ============================================================================
// ctx with inline softmax: grid (4, B, 2), 128 threads.
// Each block normalizes raw scores locally; (aid==1, hc==0) also publishes
// normalized cscores for the copy path.
// ============================================================================
__global__ void __launch_bounds__(128)
ctx_kernel(const float* __restrict__ enc,
           const float* __restrict__ cenc) {
    const int hc = blockIdx.x;
    const int b = blockIdx.y;
    const int aid = blockIdx.z;
    const int T = aid ? TC : TT;
    const int tid = threadIdx.x;

    __shared__ float sw[TT];
    __shared__ float red[32];

    float v0 = (tid < T) ? g_scores[aid][b][tid] : -INFINITY;
    float v1 = (tid + 128 < T) ? g_scores[aid][b][tid + 128] : -INFINITY;
    float m = block_reduce(fmaxf(v0, v1), red, 0);
    float e0 = (tid < T) ? __expf(v0 - m) : 0.0f;
    float e1 = (tid + 128 < T) ? __expf(v1 - m) : 0.0f;
    float ssum = block_reduce(e0 + e1, red, 1);
    float inv = 1.0f / ssum;
    if (tid < T) sw[tid] = e0 * inv;
    if (tid + 128 < T) sw[tid + 128] = e1 * inv;
    __syncthreads();

    if (aid == 1 && hc == 0) {
        if (tid < T) g_nscores[b][tid] = sw[tid];
        if (tid + 128 < T) g_nscores[b][tid + 128] = sw[tid + 128];
    }

    const float* eb = (aid ? cenc : enc) + (size_t)b * T * HH + hc * 128 + tid;
    float acc = 0.0f;
    int t = 0;
    for (; t + 4 <= T; t += 4) {
        float x0 = eb[(size_t)(t + 0) * HH];
        float x1 = eb[(size_t)(t + 1) * HH];
        float x2 = eb[(size_t)(t + 2) * HH];
        float x3 = eb[(size_t)(t + 3) * HH];
        acc += sw[t] * x0 + sw[t + 1] * x1 + sw[t + 2] * x2 + sw[t + 3] * x3;
    }
    for (; t < T; t++) acc += sw[t] * eb[(size_t)t * HH];

    float* dst = aid ? g_cctx : g_context;
    dst[(size_t)b * HH + hc * 128 + tid] = acc;
}

// ---------------- p_gen ----------------
__global__ void pgen_kernel(const float* __restrict__ h1,
                            const float* __restrict__ embedding,
                            const int* __restrict__ input,
                            const float* __restrict__ gen_W,
                            const float* __restrict__ gen_b,
                            const float* __restrict__ sig_b,
                            const int* __restrict__ context_input) {
    __shared__ float red[32];
    int b = blockIdx.x;
    int tid = threadIdx.x;
    float s = 0.0f;
    for (int k = tid; k < HH; k += 256) s += g_context[b * HH + k] * gen_W[k];
    for (int k = tid; k < HH; k += 256) s += g_cctx[b * HH + k] * gen_W[HH + k];
    for (int k = tid; k < HH; k += 256) s += h1[b * HH + k] * gen_W[2 * HH + k];
    {
        const float* emb = embedding + (size_t)input[b] * EE;
        for (int k = tid; k < EE; k += 256) s += emb[k] * gen_W[3 * HH + k];
    }
    s = block_reduce(s, red, 1);

    float cnt = 0.0f;
    for (int t = tid; t < TC; t += 256)
        cnt += (context_input[(size_t)b * TC + t] > 0) ? 1.0f : 0.0f;
    cnt = block_reduce(cnt, red, 1);

    if (tid == 0) {
        float p = sigmoidf_(s + gen_b[0] + sig_b[0]);
        if (cnt == 0.0f) p = 1.0f;
        g_pgen[b] = p;
    }
}

// ============================================================================
// write: quarter-V-range prob + copy + log: grid (4, B), 256 threads.
// Combines the 4 stats partials inline.
// ============================================================================
__global__ void __launch_bounds__(256)
write_kernel(const float* __restrict__ out_b,
             const int* __restrict__ context_input,
             float* __restrict__ out) {
    extern __shared__ float copyv[];
    const int qq = blockIdx.x;
    const int b = blockIdx.y;
    const int tid = threadIdx.x;
    const int base = qq * QWR;
    const int len = (base + QWR <= VEXT) ? QWR : (VEXT - base);

    // combine stat partials (redundant per thread; 4 tiny reads)
    float M = fmaxf(fmaxf(g_part[b][0][0], g_part[b][1][0]),
                    fmaxf(g_part[b][2][0], g_part[b][3][0]));
    float S = g_part[b][0][1] * __expf(g_part[b][0][0] - M)
            + g_part[b][1][1] * __expf(g_part[b][1][0] - M)
            + g_part[b][2][1] * __expf(g_part[b][2][0] - M)
            + g_part[b][3][1] * __expf(g_part[b][3][0] - M);
    const float pg = g_pgen[b];
    const float scale = pg / S;

    for (int v = tid; v < len; v += 256) copyv[v] = 0.0f;
    __syncthreads();

    if (tid < TC) {
        int idx = context_input[(size_t)b * TC + tid];
        if (idx >= base && idx < base + len) {
            float w = (1.0f - pg) * g_nscores[b][tid];
            atomicAdd(&copyv[idx - base], w);
        }
    }
    __syncthreads();

    const float* lg = g_logits + (size_t)b * LPAD;
    float* row = out + (size_t)b * VEXT;

    const int vend = (base + len < VV) ? (base + len) : VV;
    for (int v = base + tid; v < vend; v += 256) {
        float p = __expf(lg[v] + out_b[v] - M) * scale + copyv[v - base];
        row[v] = __logf(fmaxf(p, 1e-10f));
    }
    for (int v = (VV > base ? VV : base) + tid; v < base + len; v += 256)
        row[v] = __logf(fmaxf(copyv[v - base], 1e-10f));
}

// ---------------- launcher ----------------
extern "C" void kernel_launch(void* const* d_in, const int* in_sizes, int n_in,
                              void* d_out, int out_size) {
    const int*   input    = (const int*)  d_in[0];
    const float* h0       = (const float*)d_in[1];
    const float* c0       = (const float*)d_in[2];
    const float* enc      = (const float*)d_in[3];
    const float* cenc     = (const float*)d_in[4];
    const int*   ctx_in   = (const int*)  d_in[5];
    const float* embedding= (const float*)d_in[6];
    const float* W_ih     = (const float*)d_in[7];
    const float* W_hh     = (const float*)d_in[8];
    const float* b_ih     = (const float*)d_in[9];
    const float* b_hh     = (const float*)d_in[10];
    const float* attn_W   = (const float*)d_in[11];
    const float* attn_b   = (const float*)d_in[12];
    const float* cattn_W  = (const float*)d_in[13];
    const float* cattn_b  = (const float*)d_in[14];
    const float* gen_W    = (const float*)d_in[15];
    const float* gen_b    = (const float*)d_in[16];
    const float* sig_b    = (const float*)d_in[17];
    const float* out_W    = (const float*)d_in[18];
    const float* out_b    = (const float*)d_in[19];

    float* out = (float*)d_out;
    float* logp   = out;
    float* h1_out = out + (size_t)BB * VEXT;
    float* c1_out = h1_out + (size_t)BB * HH;

    float* d_gates;  cudaGetSymbolAddress((void**)&d_gates,  g_gates);
    float* d_dec2;   cudaGetSymbolAddress((void**)&d_dec2,   g_dec2);
    float* d_logits; cudaGetSymbolAddress((void**)&d_logits, g_logits);

    const int SMEM64  = NSTG * (128 + 64) * ASTR * 4;   // 82944
    const int SMEM_WRITE = QWR * 4 + 64;                // ~50116
    cudaFuncSetAttribute(gemm_tc<64>,
        cudaFuncAttributeMaxDynamicSharedMemorySize, SMEM64);
    cudaFuncSetAttribute(write_kernel,
        cudaFuncAttributeMaxDynamicSharedMemorySize, SMEM_WRITE);

    // 1) gates = [emb | h0] @ [W_ih | W_hh]^T
    gemm_tc<64><<<H4 / 64, 256, SMEM64>>>(
        embedding, EE, h0, HH, input,
        W_ih, EE, W_hh, HH, EE,
        d_gates, H4, H4, EE + HH);

    // 2) LSTM pointwise -> h1, c1 (into d_out tail)
    lstm_kernel<<<(BB * HH + 255) / 256, 256>>>(c0, b_ih, b_hh, h1_out, c1_out);

    // 3) mega fp16 GEMM: logits + dec2 in one launch
    mega_fp16<<<NLOGIT + NDEC, 256>>>(h1_out, out_W, attn_W, cattn_W,
                                      d_logits, d_dec2);

    // 4) merged: attention scores + softmax stats partials [ncu slot]
    scores_stats<<<NSCORE + 4 * BB, 256>>>(enc, cenc, attn_b, cattn_b, out_b);

    // 5) contexts with inline softmax (+ publish normalized cscores)
    ctx_kernel<<<dim3(4, BB, 2), 128>>>(enc, cenc);

    // 6) p_gen
    pgen_kernel<<<BB, 256>>>(h1_out, embedding, input, gen_W, gen_b, sig_b, ctx_in);

    // 7) fused prob + copy-scatter + log, quarter split
    write_kernel<<<dim3(4, BB), 256, SMEM_WRITE>>>(out_b, ctx_in, logp);
}

// round 11
// speedup vs baseline: 2.1454x; 1.1685x over previous
#include <cuda_runtime.h>
#include <cuda_fp16.h>
#include <mma.h>
#include <math.h>
#include <cstdint>

using namespace nvcuda;

// ---------------- problem constants ----------------
#define BB   128
#define TT   256
#define TC   200
#define EE   256
#define HH   512
#define H4   2048
#define VV   50000
#define MAX_OOV 50
#define VEXT 50050
#define LPAD 50176   // padded logits row stride

#define QSTAT 12500  // stats partial range (VV/4)
#define QWR   12513  // write quarter range (ceil VEXT/4)

#define ASTR 36      // tf32 gemm smem row stride (floats)
#define NSTG 3       // tf32 gemm cp.async stages

#define NLOGIT (LPAD / 128)        // 392 logits blocks
#define NDEC   8                   // dec2 blocks (N=1024)

#define FCH 16                     // flash-attn chunk rows
// flash smem layout (floats): sdec[512] | sraw[256] | sc[16] | swc[16] | chunk[2][16*512]
#define FS_SDEC  0
#define FS_SRAW  512
#define FS_SC    (512 + 256)
#define FS_SWC   (512 + 256 + 16)
#define FS_CHUNK (512 + 256 + 32)
#define FS_TOTAL (FS_CHUNK + 2 * FCH * HH)   // 17184 floats = 68736 B

// ---------------- scratch (device globals; no allocation) ----------------
__device__ float g_gates[BB * H4];
__device__ float g_dec2[BB * 1024];        // [dec | cdec] per row
__device__ float g_context[BB * HH];
__device__ float g_cctx[BB * HH];
__device__ float g_nscores[BB][TT];        // normalized cscores (attn 1)
__device__ float g_pgen[BB];
__device__ float g_part[BB][4][2];         // per-quarter online {m, s}
__device__ float g_logits[BB * LPAD];

__device__ __forceinline__ float sigmoidf_(float x) {
    return 1.0f / (1.0f + __expf(-x));
}

// ---------------- cp.async helpers ----------------
__device__ __forceinline__ void cp_async16(uint32_t dst, const void* src) {
    asm volatile("cp.async.cg.shared.global [%0], [%1], 16;\n" :: "r"(dst), "l"(src));
}
__device__ __forceinline__ void cp_commit() {
    asm volatile("cp.async.commit_group;\n" ::);
}
template <int N>
__device__ __forceinline__ void cp_wait() {
    asm volatile("cp.async.wait_group %0;\n" :: "n"(N));
}

// block reduce: op 0 = max, 1 = sum (blockDim <= 1024)
__device__ __forceinline__ float block_reduce(float v, float* red, int op) {
    int lane = threadIdx.x & 31, warp = threadIdx.x >> 5;
    #pragma unroll
    for (int o = 16; o > 0; o >>= 1) {
        float u = __shfl_xor_sync(0xffffffffu, v, o);
        v = op ? (v + u) : fmaxf(v, u);
    }
    if (lane == 0) red[warp] = v;
    __syncthreads();
    int nw = (blockDim.x + 31) >> 5;
    if (warp == 0) {
        v = (lane < nw) ? red[lane] : (op ? 0.0f : -INFINITY);
        #pragma unroll
        for (int o = 16; o > 0; o >>= 1) {
            float u = __shfl_xor_sync(0xffffffffu, v, o);
            v = op ? (v + u) : fmaxf(v, u);
        }
        if (lane == 0) red[0] = v;
    }
    __syncthreads();
    float r = red[0];
    __syncthreads();
    return r;
}

// ============================================================================
// Mega fp16 wmma GEMM (one launch): logits blocks + dec2 blocks.
// ============================================================================
__global__ void __launch_bounds__(256)
mega_fp16(const float* __restrict__ A,        // h1 [128,512]
          const float* __restrict__ Wout,     // [VV,512]
          const float* __restrict__ Wattn,    // [512,512]
          const float* __restrict__ Wcattn,   // [512,512]
          float* __restrict__ Clog,           // g_logits
          float* __restrict__ Cdec) {         // g_dec2
    __shared__ __half As[2][128][40];
    __shared__ __half Ws[2][128][40];

    const int tid = threadIdx.x;
    const int wid = tid >> 5;
    const int warp_m = wid >> 2;
    const int warp_n = wid & 3;
    const bool is_dec = (blockIdx.x >= NLOGIT);
    const int n0 = (is_dec ? (int)blockIdx.x - NLOGIT : (int)blockIdx.x) * 128;
    float* C = is_dec ? Cdec : Clog;
    const int ldc = is_dec ? 1024 : LPAD;
    const int KT = 16;

    float4 ra[4], rw[4];

    auto wrow = [&](int nr) -> const float* {
        if (is_dec)
            return (nr < 512) ? Wattn + (size_t)nr * HH
                              : Wcattn + (size_t)(nr - 512) * HH;
        if (nr >= VV) nr = VV - 1;
        return Wout + (size_t)nr * HH;
    };

    auto ldg_stage = [&](int kt) {
        #pragma unroll
        for (int r = 0; r < 4; r++) {
            int f = tid + r * 256;
            int row = f >> 3, q = f & 7;
            ra[r] = *reinterpret_cast<const float4*>(
                A + (size_t)row * HH + kt * 32 + q * 4);
            rw[r] = *reinterpret_cast<const float4*>(
                wrow(n0 + row) + kt * 32 + q * 4);
        }
    };
    auto sts_stage = [&](int s) {
        #pragma unroll
        for (int r = 0; r < 4; r++) {
            int f = tid + r * 256;
            int row = f >> 3, q = f & 7;
            *reinterpret_cast<__half2*>(&As[s][row][q * 4]) =
                __floats2half2_rn(ra[r].x, ra[r].y);
            *reinterpret_cast<__half2*>(&As[s][row][q * 4 + 2]) =
                __floats2half2_rn(ra[r].z, ra[r].w);
            *reinterpret_cast<__half2*>(&Ws[s][row][q * 4]) =
                __floats2half2_rn(rw[r].x, rw[r].y);
            *reinterpret_cast<__half2*>(&Ws[s][row][q * 4 + 2]) =
                __floats2half2_rn(rw[r].z, rw[r].w);
        }
    };

    wmma::fragment<wmma::accumulator, 16, 16, 16, float> c[4][2];
    #pragma unroll
    for (int i = 0; i < 4; i++)
        #pragma unroll
        for (int j = 0; j < 2; j++) wmma::fill_fragment(c[i][j], 0.0f);

    ldg_stage(0);
    sts_stage(0);
    ldg_stage(1);
    __syncthreads();

    for (int kt = 0; kt < KT; kt++) {
        if (kt + 1 < KT) sts_stage((kt + 1) & 1);
        if (kt + 2 < KT) ldg_stage(kt + 2);

        const int s = kt & 1;
        #pragma unroll
        for (int k16 = 0; k16 < 32; k16 += 16) {
            wmma::fragment<wmma::matrix_a, 16, 16, 16, __half,
                           wmma::row_major> a[4];
            wmma::fragment<wmma::matrix_b, 16, 16, 16, __half,
                           wmma::col_major> b[2];
            #pragma unroll
            for (int mi = 0; mi < 4; mi++)
                wmma::load_matrix_sync(a[mi],
                    &As[s][warp_m * 64 + mi * 16][k16], 40);
            #pragma unroll
            for (int ni = 0; ni < 2; ni++)
                wmma::load_matrix_sync(b[ni],
                    &Ws[s][warp_n * 32 + ni * 16][k16], 40);
            #pragma unroll
            for (int mi = 0; mi < 4; mi++)
                #pragma unroll
                for (int ni = 0; ni < 2; ni++)
                    wmma::mma_sync(c[mi][ni], a[mi], b[ni], c[mi][ni]);
        }
        __syncthreads();
    }

    #pragma unroll
    for (int mi = 0; mi < 4; mi++)
        #pragma unroll
        for (int ni = 0; ni < 2; ni++)
            wmma::store_matrix_sync(
                &C[(size_t)(warp_m * 64 + mi * 16) * ldc + n0 + warp_n * 32 + ni * 16],
                c[mi][ni], ldc, wmma::mem_row_major);
}

// ============================================================================
// wmma tf32 GEMM (gates)
// ============================================================================
template <int BN>
__global__ void __launch_bounds__(256, 2)
gemm_tc(const float* __restrict__ A1, int lda1,
        const float* __restrict__ A2, int lda2,
        const int* __restrict__ gather_idx,
        const float* __restrict__ W1, int ldw1,
        const float* __restrict__ W2, int ldw2, int K1,
        float* __restrict__ C, int ldc,
        int N, int K) {
    extern __shared__ float smem[];
    float* As = smem;
    float* Ws = smem + NSTG * 128 * ASTR;

    const int tid = threadIdx.x;
    const int wid = tid >> 5;
    const int warp_m = wid >> 1;
    const int warp_n = wid & 1;
    const int n0 = blockIdx.x * BN;
    constexpr int WN = BN / 2;
    constexpr int NI = WN / 16;
    const int KT = K >> 5;

    const uint32_t as_base = (uint32_t)__cvta_generic_to_shared(As);
    const uint32_t ws_base = (uint32_t)__cvta_generic_to_shared(Ws);

    auto issue_stage = [&](int kt, int s) {
        const int kk = kt << 5;
        #pragma unroll
        for (int r = 0; r < 4; r++) {
            int f = tid + r * 256;
            int row = f >> 3, kq = f & 7;
            int k = kk + kq * 4;
            const float* src;
            if (k < K1) {
                int arow = gather_idx ? gather_idx[row] : row;
                src = A1 + (size_t)arow * lda1 + k;
            } else {
                src = A2 + (size_t)row * lda2 + (k - K1);
            }
            cp_async16(as_base + (uint32_t)((s * 128 + row) * ASTR + kq * 4) * 4, src);
        }
        #pragma unroll
        for (int r = 0; r < BN / 32; r++) {
            int f = tid + r * 256;
            int row = f >> 3, kq = f & 7;
            int k = kk + kq * 4;
            int nr = n0 + row;
            if (nr >= N) nr = N - 1;
            const float* src = (k < K1)
                ? W1 + (size_t)nr * ldw1 + k
                : W2 + (size_t)nr * ldw2 + (k - K1);
            cp_async16(ws_base + (uint32_t)((s * BN + row) * ASTR + kq * 4) * 4, src);
        }
        cp_commit();
    };

    wmma::fragment<wmma::accumulator, 16, 16, 8, float> c[2][NI];
    #pragma unroll
    for (int i = 0; i < 2; i++)
        #pragma unroll
        for (int j = 0; j < NI; j++) wmma::fill_fragment(c[i][j], 0.0f);

    issue_stage(0, 0);
    if (KT > 1) issue_stage(1, 1);

    for (int kt = 0; kt < KT; kt++) {
        if (kt + 2 < KT) {
            issue_stage(kt + 2, (kt + 2) % NSTG);
            cp_wait<2>();
        } else if (kt + 1 < KT) {
            cp_wait<1>();
        } else {
            cp_wait<0>();
        }
        __syncthreads();

        const int s = kt % NSTG;
        const float* as = As + (size_t)s * 128 * ASTR;
        const float* ws = Ws + (size_t)s * BN * ASTR;

        #pragma unroll
        for (int k8 = 0; k8 < 32; k8 += 8) {
            wmma::fragment<wmma::matrix_a, 16, 16, 8, wmma::precision::tf32,
                           wmma::row_major> a[2];
            wmma::fragment<wmma::matrix_b, 16, 16, 8, wmma::precision::tf32,
                           wmma::col_major> b[NI];
            #pragma unroll
            for (int mi = 0; mi < 2; mi++)
                wmma::load_matrix_sync(a[mi],
                    as + (warp_m * 32 + mi * 16) * ASTR + k8, ASTR);
            #pragma unroll
            for (int ni = 0; ni < NI; ni++)
                wmma::load_matrix_sync(b[ni],
                    ws + (warp_n * WN + ni * 16) * ASTR + k8, ASTR);
            #pragma unroll
            for (int mi = 0; mi < 2; mi++)
                #pragma unroll
                for (int ni = 0; ni < NI; ni++)
                    wmma::mma_sync(c[mi][ni], a[mi], b[ni], c[mi][ni]);
        }
        __syncthreads();
    }

    #pragma unroll
    for (int mi = 0; mi < 2; mi++)
        #pragma unroll
        for (int ni = 0; ni < NI; ni++)
            wmma::store_matrix_sync(
                &C[(size_t)(warp_m * 32 + mi * 16) * ldc + n0 + warp_n * WN + ni * 16],
                c[mi][ni], ldc, wmma::mem_row_major);
}

// ---------------- LSTM pointwise ----------------
__global__ void lstm_kernel(const float* __restrict__ c0,
                            const float* __restrict__ b_ih,
                            const float* __restrict__ b_hh,
                            float* __restrict__ h1_out,
                            float* __restrict__ c1_out) {
    int i = blockIdx.x * blockDim.x + threadIdx.x;
    if (i >= BB * HH) return;
    int b = i / HH, h = i % HH;
    const float* g = g_gates + (size_t)b * H4;
    float gi = g[h]          + b_ih[h]          + b_hh[h];
    float gf = g[HH + h]     + b_ih[HH + h]     + b_hh[HH + h];
    float gg = g[2 * HH + h] + b_ih[2 * HH + h] + b_hh[2 * HH + h];
    float go = g[3 * HH + h] + b_ih[3 * HH + h] + b_hh[3 * HH + h];
    float c = sigmoidf_(gf) * c0[i] + sigmoidf_(gi) * tanhf(gg);
    float hh = sigmoidf_(go) * tanhf(c);
    c1_out[i] = c;
    h1_out[i] = hh;
}

// ============================================================================
// Merged launch: flash attention (blocks [0, 2B)) + stats quarters (next 4B).
// 256 threads. Flash: one block per (b, aid); enc read EXACTLY ONCE via
// double-buffered cp.async chunks with online softmax + rescaled ctx accum.
// ============================================================================
__global__ void __launch_bounds__(256)
flash_stats(const float* __restrict__ enc,
            const float* __restrict__ cenc,
            const float* __restrict__ attn_b,
            const float* __restrict__ cattn_b,
            const float* __restrict__ out_b) {
    extern __shared__ float fs[];
    const int tid = threadIdx.x;

    if (blockIdx.x < 2 * BB) {
        const int aid = blockIdx.x >> 7;       // 0/1
        const int b = blockIdx.x & 127;
        const int T = aid ? TC : TT;
        const int NC = (T + FCH - 1) / FCH;
        const float* eb = (aid ? cenc : enc) + (size_t)b * T * HH;

        float* sdec = fs + FS_SDEC;
        float* sraw = fs + FS_SRAW;
        float* sc   = fs + FS_SC;
        float* swc  = fs + FS_SWC;
        float* chunk = fs + FS_CHUNK;          // [2][FCH*HH]
        const uint32_t ch_base = (uint32_t)__cvta_generic_to_shared(chunk);

        {
            const float* dec = g_dec2 + (size_t)b * 1024 + aid * HH;
            const float* bias = aid ? cattn_b : attn_b;
            sdec[tid] = dec[tid] + bias[tid];
            sdec[tid + 256] = dec[tid + 256] + bias[tid + 256];
        }

        auto issue_chunk = [&](int c) {
            const int s = c & 1;
            const int t0 = c * FCH;
            #pragma unroll
            for (int r = 0; r < 8; r++) {
                int f = tid + r * 256;         // 0..2047
                int row = f >> 7;              // 0..15 (128 float4 per row)
                int c4 = f & 127;
                int t = t0 + row;
                if (t >= T) t = T - 1;
                cp_async16(ch_base + (uint32_t)(s * FCH * HH + row * HH + c4 * 4) * 4,
                           eb + (size_t)t * HH + c4 * 4);
            }
            cp_commit();
        };

        issue_chunk(0);
        __syncthreads();   // sdec visible to all

        float acc0 = 0.0f, acc1 = 0.0f;
        float m = -INFINITY, ssum = 0.0f;
        const int warp = tid >> 5, lane = tid & 31;

        for (int c = 0; c < NC; c++) {
            if (c + 1 < NC) {
                issue_chunk(c + 1);
                cp_wait<1>();
            } else {
                cp_wait<0>();
            }
            __syncthreads();

            const float* ch = chunk + (c & 1) * FCH * HH;
            const int t0 = c * FCH;

            // scores: warp w -> rows w, w+8
            #pragma unroll
            for (int rr = 0; rr < 2; rr++) {
                int row = warp + rr * 8;
                int t = t0 + row;
                const float4* rp = reinterpret_cast<const float4*>(ch + row * HH);
                float s = 0.0f;
                #pragma unroll
                for (int q = 0; q < 4; q++) {
                    int f4 = lane + 32 * q;
                    float4 v = rp[f4];
                    s += v.x * sdec[f4 * 4 + 0] + v.y * sdec[f4 * 4 + 1] +
                         v.z * sdec[f4 * 4 + 2] + v.w * sdec[f4 * 4 + 3];
                }
                #pragma unroll
                for (int o = 16; o > 0; o >>= 1)
                    s += __shfl_xor_sync(0xffffffffu, s, o);
                if (lane == 0) {
                    sc[row] = (t < T) ? s : -INFINITY;
                    if (t < T) sraw[t] = s;
                }
            }
            __syncthreads();

            // online update (per-thread replicated bookkeeping from smem)
            float mc = sc[0];
            #pragma unroll
            for (int t = 1; t < FCH; t++) mc = fmaxf(mc, sc[t]);
            float newm = fmaxf(m, mc);
            if (tid < FCH)
                swc[tid] = (sc[tid] == -INFINITY) ? 0.0f : __expf(sc[tid] - newm);
            __syncthreads();

            float f = (m == -INFINITY) ? 0.0f : __expf(m - newm);
            acc0 *= f;
            acc1 *= f;
            float wsum = 0.0f;
            #pragma unroll
            for (int t = 0; t < FCH; t++) {
                float w = swc[t];
                wsum += w;
                acc0 += w * ch[t * HH + tid];
                acc1 += w * ch[t * HH + tid + 256];
            }
            ssum = ssum * f + wsum;
            m = newm;
            __syncthreads();
        }

        float inv = 1.0f / ssum;
        float* dst = aid ? g_cctx : g_context;
        dst[(size_t)b * HH + tid] = acc0 * inv;
        dst[(size_t)b * HH + tid + 256] = acc1 * inv;

        if (aid == 1) {
            if (tid < T) g_nscores[b][tid] = __expf(sraw[tid] - m) * inv;
        }
    } else {
        // ---- stats quarter: online (m, s) over logits+bias ----
        const int idx = blockIdx.x - 2 * BB;
        const int q = idx & 3;
        const int b = idx >> 2;
        const int v0 = q * QSTAT;
        const int v1 = (q == 3) ? VV : v0 + QSTAT;
        const float* lg = g_logits + (size_t)b * LPAD;
        float* red = fs;   // 32 floats scratch

        float m = -INFINITY, s = 0.0f;
        for (int v = v0 + tid; v < v1; v += 256) {
            float x = lg[v] + out_b[v];
            if (x > m) {
                s = s * __expf(m - x) + 1.0f;
                m = x;
            } else {
                s += __expf(x - m);
            }
        }
        float M = block_reduce(m, red, 0);
        s = (m == -INFINITY) ? 0.0f : s * __expf(m - M);
        float S = block_reduce(s, red, 1);
        if (tid == 0) {
            g_part[b][q][0] = M;
            g_part[b][q][1] = S;
        }
    }
}

// ---------------- p_gen ----------------
__global__ void pgen_kernel(const float* __restrict__ h1,
                            const float* __restrict__ embedding,
                            const int* __restrict__ input,
                            const float* __restrict__ gen_W,
                            const float* __restrict__ gen_b,
                            const float* __restrict__ sig_b,
                            const int* __restrict__ context_input) {
    __shared__ float red[32];
    int b = blockIdx.x;
    int tid = threadIdx.x;
    float s = 0.0f;
    for (int k = tid; k < HH; k += 256) s += g_context[b * HH + k] * gen_W[k];
    for (int k = tid; k < HH; k += 256) s += g_cctx[b * HH + k] * gen_W[HH + k];
    for (int k = tid; k < HH; k += 256) s += h1[b * HH + k] * gen_W[2 * HH + k];
    {
        const float* emb = embedding + (size_t)input[b] * EE;
        for (int k = tid; k < EE; k += 256) s += emb[k] * gen_W[3 * HH + k];
    }
    s = block_reduce(s, red, 1);

    float cnt = 0.0f;
    for (int t = tid; t < TC; t += 256)
        cnt += (context_input[(size_t)b * TC + t] > 0) ? 1.0f : 0.0f;
    cnt = block_reduce(cnt, red, 1);

    if (tid == 0) {
        float p = sigmoidf_(s + gen_b[0] + sig_b[0]);
        if (cnt == 0.0f) p = 1.0f;
        g_pgen[b] = p;
    }
}

// ============================================================================
// write: quarter-V-range prob + copy + log: grid (4, B), 256 threads.
// ============================================================================
__global__ void __launch_bounds__(256)
write_kernel(const float* __restrict__ out_b,
             const int* __restrict__ context_input,
             float* __restrict__ out) {
    extern __shared__ float copyv[];
    const int qq = blockIdx.x;
    const int b = blockIdx.y;
    const int tid = threadIdx.x;
    const int base = qq * QWR;
    const int len = (base + QWR <= VEXT) ? QWR : (VEXT - base);

    float M = fmaxf(fmaxf(g_part[b][0][0], g_part[b][1][0]),
                    fmaxf(g_part[b][2][0], g_part[b][3][0]));
    float S = g_part[b][0][1] * __expf(g_part[b][0][0] - M)
            + g_part[b][1][1] * __expf(g_part[b][1][0] - M)
            + g_part[b][2][1] * __expf(g_part[b][2][0] - M)
            + g_part[b][3][1] * __expf(g_part[b][3][0] - M);
    const float pg = g_pgen[b];
    const float scale = pg / S;

    for (int v = tid; v < len; v += 256) copyv[v] = 0.0f;
    __syncthreads();

    if (tid < TC) {
        int idx = context_input[(size_t)b * TC + tid];
        if (idx >= base && idx < base + len) {
            float w = (1.0f - pg) * g_nscores[b][tid];
            atomicAdd(&copyv[idx - base], w);
        }
    }
    __syncthreads();

    const float* lg = g_logits + (size_t)b * LPAD;
    float* row = out + (size_t)b * VEXT;

    const int vend = (base + len < VV) ? (base + len) : VV;
    for (int v = base + tid; v < vend; v += 256) {
        float p = __expf(lg[v] + out_b[v] - M) * scale + copyv[v - base];
        row[v] = __logf(fmaxf(p, 1e-10f));
    }
    for (int v = (VV > base ? VV : base) + tid; v < base + len; v += 256)
        row[v] = __logf(fmaxf(copyv[v - base], 1e-10f));
}

// ---------------- launcher ----------------
extern "C" void kernel_launch(void* const* d_in, const int* in_sizes, int n_in,
                              void* d_out, int out_size) {
    const int*   input    = (const int*)  d_in[0];
    const float* h0       = (const float*)d_in[1];
    const float* c0       = (const float*)d_in[2];
    const float* enc      = (const float*)d_in[3];
    const float* cenc     = (const float*)d_in[4];
    const int*   ctx_in   = (const int*)  d_in[5];
    const float* embedding= (const float*)d_in[6];
    const float* W_ih     = (const float*)d_in[7];
    const float* W_hh     = (const float*)d_in[8];
    const float* b_ih     = (const float*)d_in[9];
    const float* b_hh     = (const float*)d_in[10];
    const float* attn_W   = (const float*)d_in[11];
    const float* attn_b   = (const float*)d_in[12];
    const float* cattn_W  = (const float*)d_in[13];
    const float* cattn_b  = (const float*)d_in[14];
    const float* gen_W    = (const float*)d_in[15];
    const float* gen_b    = (const float*)d_in[16];
    const float* sig_b    = (const float*)d_in[17];
    const float* out_W    = (const float*)d_in[18];
    const float* out_b    = (const float*)d_in[19];

    float* out = (float*)d_out;
    float* logp   = out;
    float* h1_out = out + (size_t)BB * VEXT;
    float* c1_out = h1_out + (size_t)BB * HH;

    float* d_gates;  cudaGetSymbolAddress((void**)&d_gates,  g_gates);
    float* d_dec2;   cudaGetSymbolAddress((void**)&d_dec2,   g_dec2);
    float* d_logits; cudaGetSymbolAddress((void**)&d_logits, g_logits);

    const int SMEM64    = NSTG * (128 + 64) * ASTR * 4;  // 82944
    const int SMEM_FL   = FS_TOTAL * 4;                  // 68736
    const int SMEM_WRITE = QWR * 4 + 64;                 // ~50116
    cudaFuncSetAttribute(gemm_tc<64>,
        cudaFuncAttributeMaxDynamicSharedMemorySize, SMEM64);
    cudaFuncSetAttribute(flash_stats,
        cudaFuncAttributeMaxDynamicSharedMemorySize, SMEM_FL);
    cudaFuncSetAttribute(write_kernel,
        cudaFuncAttributeMaxDynamicSharedMemorySize, SMEM_WRITE);

    // 1) gates = [emb | h0] @ [W_ih | W_hh]^T
    gemm_tc<64><<<H4 / 64, 256, SMEM64>>>(
        embedding, EE, h0, HH, input,
        W_ih, EE, W_hh, HH, EE,
        d_gates, H4, H4, EE + HH);

    // 2) LSTM pointwise -> h1, c1 (into d_out tail)
    lstm_kernel<<<(BB * HH + 255) / 256, 256>>>(c0, b_ih, b_hh, h1_out, c1_out);

    // 3) mega fp16 GEMM: logits + dec2 in one launch
    mega_fp16<<<NLOGIT + NDEC, 256>>>(h1_out, out_W, attn_W, cattn_W,
                                      d_logits, d_dec2);

    // 4) flash attention (enc read once) + softmax stats partials [ncu slot]
    flash_stats<<<2 * BB + 4 * BB, 256, SMEM_FL>>>(
        enc, cenc, attn_b, cattn_b, out_b);

    // 5) p_gen
    pgen_kernel<<<BB, 256>>>(h1_out, embedding, input, gen_W, gen_b, sig_b, ctx_in);

    // 6) fused prob + copy-scatter + log, quarter split
    write_kernel<<<dim3(4, BB), 256, SMEM_WRITE>>>(out_b, ctx_in, logp);
}

// round 12
// speedup vs baseline: 2.2161x; 1.0330x over previous
#include <cuda_runtime.h>
#include <cuda_fp16.h>
#include <mma.h>
#include <math.h>
#include <cstdint>

using namespace nvcuda;

// ---------------- problem constants ----------------
#define BB   128
#define TT   256
#define TC   200
#define EE   256
#define HH   512
#define H4   2048
#define VV   50000
#define MAX_OOV 50
#define VEXT 50050
#define LPAD 50176   // padded logits row stride

#define QSTAT 12500  // stats partial range (VV/4)
#define QWR   12513  // write quarter range (ceil VEXT/4)

#define ASTR 36      // tf32 gemm smem row stride (floats)
#define NSTG 3       // tf32 gemm cp.async stages

#define NLOGIT (LPAD / 128)        // 392 logits blocks
#define NDEC   8                   // dec2 blocks (N=1024)

#define FCH 16                     // flash-attn chunk rows
#define FS_SDEC  0
#define FS_SRAW  512
#define FS_SC    (512 + 256)
#define FS_SWC   (512 + 256 + 16)
#define FS_CHUNK (512 + 256 + 32)
#define FS_TOTAL (FS_CHUNK + 2 * FCH * HH)   // 17184 floats = 68736 B

// ---------------- scratch (device globals; no allocation) ----------------
__device__ float g_gates[BB * H4];
__device__ float g_dec2[BB * 1024];        // [dec | cdec] per row
__device__ float g_context[BB * HH];
__device__ float g_cctx[BB * HH];
__device__ float g_nscores[BB][TT];        // normalized cscores (attn 1)
__device__ float g_part[BB][4][2];         // per-quarter online {m, s}
__device__ __half g_logits_h[BB * LPAD];   // fp16 logits (12.8 MB)

__device__ __forceinline__ float sigmoidf_(float x) {
    return 1.0f / (1.0f + __expf(-x));
}

// ---------------- cp.async helpers ----------------
__device__ __forceinline__ void cp_async16(uint32_t dst, const void* src) {
    asm volatile("cp.async.cg.shared.global [%0], [%1], 16;\n" :: "r"(dst), "l"(src));
}
__device__ __forceinline__ void cp_commit() {
    asm volatile("cp.async.commit_group;\n" ::);
}
template <int N>
__device__ __forceinline__ void cp_wait() {
    asm volatile("cp.async.wait_group %0;\n" :: "n"(N));
}

// block reduce: op 0 = max, 1 = sum (blockDim <= 1024)
__device__ __forceinline__ float block_reduce(float v, float* red, int op) {
    int lane = threadIdx.x & 31, warp = threadIdx.x >> 5;
    #pragma unroll
    for (int o = 16; o > 0; o >>= 1) {
        float u = __shfl_xor_sync(0xffffffffu, v, o);
        v = op ? (v + u) : fmaxf(v, u);
    }
    if (lane == 0) red[warp] = v;
    __syncthreads();
    int nw = (blockDim.x + 31) >> 5;
    if (warp == 0) {
        v = (lane < nw) ? red[lane] : (op ? 0.0f : -INFINITY);
        #pragma unroll
        for (int o = 16; o > 0; o >>= 1) {
            float u = __shfl_xor_sync(0xffffffffu, v, o);
            v = op ? (v + u) : fmaxf(v, u);
        }
        if (lane == 0) red[0] = v;
    }
    __syncthreads();
    float r = red[0];
    __syncthreads();
    return r;
}

// ============================================================================
// Mega fp16 wmma GEMM (one launch): logits blocks (half output) + dec2 blocks
// (float output). 256 threads (8 warps, 2x4), warp tile 64x32, reg prefetch.
// ============================================================================
__global__ void __launch_bounds__(256)
mega_fp16(const float* __restrict__ A,        // h1 [128,512]
          const float* __restrict__ Wout,     // [VV,512]
          const float* __restrict__ Wattn,    // [512,512]
          const float* __restrict__ Wcattn,   // [512,512]
          __half* __restrict__ Clog,          // g_logits_h
          float* __restrict__ Cdec) {         // g_dec2
    __shared__ __half As[2][128][40];
    __shared__ __half Ws[2][128][40];

    const int tid = threadIdx.x;
    const int wid = tid >> 5;
    const int warp_m = wid >> 2;
    const int warp_n = wid & 3;
    const bool is_dec = (blockIdx.x >= NLOGIT);
    const int n0 = (is_dec ? (int)blockIdx.x - NLOGIT : (int)blockIdx.x) * 128;
    const int KT = 16;

    float4 ra[4], rw[4];

    auto wrow = [&](int nr) -> const float* {
        if (is_dec)
            return (nr < 512) ? Wattn + (size_t)nr * HH
                              : Wcattn + (size_t)(nr - 512) * HH;
        if (nr >= VV) nr = VV - 1;
        return Wout + (size_t)nr * HH;
    };

    auto ldg_stage = [&](int kt) {
        #pragma unroll
        for (int r = 0; r < 4; r++) {
            int f = tid + r * 256;
            int row = f >> 3, q = f & 7;
            ra[r] = *reinterpret_cast<const float4*>(
                A + (size_t)row * HH + kt * 32 + q * 4);
            rw[r] = *reinterpret_cast<const float4*>(
                wrow(n0 + row) + kt * 32 + q * 4);
        }
    };
    auto sts_stage = [&](int s) {
        #pragma unroll
        for (int r = 0; r < 4; r++) {
            int f = tid + r * 256;
            int row = f >> 3, q = f & 7;
            *reinterpret_cast<__half2*>(&As[s][row][q * 4]) =
                __floats2half2_rn(ra[r].x, ra[r].y);
            *reinterpret_cast<__half2*>(&As[s][row][q * 4 + 2]) =
                __floats2half2_rn(ra[r].z, ra[r].w);
            *reinterpret_cast<__half2*>(&Ws[s][row][q * 4]) =
                __floats2half2_rn(rw[r].x, rw[r].y);
            *reinterpret_cast<__half2*>(&Ws[s][row][q * 4 + 2]) =
                __floats2half2_rn(rw[r].z, rw[r].w);
        }
    };

    wmma::fragment<wmma::accumulator, 16, 16, 16, float> c[4][2];
    #pragma unroll
    for (int i = 0; i < 4; i++)
        #pragma unroll
        for (int j = 0; j < 2; j++) wmma::fill_fragment(c[i][j], 0.0f);

    ldg_stage(0);
    sts_stage(0);
    ldg_stage(1);
    __syncthreads();

    for (int kt = 0; kt < KT; kt++) {
        if (kt + 1 < KT) sts_stage((kt + 1) & 1);
        if (kt + 2 < KT) ldg_stage(kt + 2);

        const int s = kt & 1;
        #pragma unroll
        for (int k16 = 0; k16 < 32; k16 += 16) {
            wmma::fragment<wmma::matrix_a, 16, 16, 16, __half,
                           wmma::row_major> a[4];
            wmma::fragment<wmma::matrix_b, 16, 16, 16, __half,
                           wmma::col_major> b[2];
            #pragma unroll
            for (int mi = 0; mi < 4; mi++)
                wmma::load_matrix_sync(a[mi],
                    &As[s][warp_m * 64 + mi * 16][k16], 40);
            #pragma unroll
            for (int ni = 0; ni < 2; ni++)
                wmma::load_matrix_sync(b[ni],
                    &Ws[s][warp_n * 32 + ni * 16][k16], 40);
            #pragma unroll
            for (int mi = 0; mi < 4; mi++)
                #pragma unroll
                for (int ni = 0; ni < 2; ni++)
                    wmma::mma_sync(c[mi][ni], a[mi], b[ni], c[mi][ni]);
        }
        __syncthreads();
    }

    #pragma unroll
    for (int mi = 0; mi < 4; mi++)
        #pragma unroll
        for (int ni = 0; ni < 2; ni++) {
            const int ro = warp_m * 64 + mi * 16;
            const int co = n0 + warp_n * 32 + ni * 16;
            if (is_dec) {
                wmma::store_matrix_sync(&Cdec[(size_t)ro * 1024 + co],
                                        c[mi][ni], 1024, wmma::mem_row_major);
            } else {
                wmma::fragment<wmma::accumulator, 16, 16, 16, __half> hc;
                #pragma unroll
                for (int e = 0; e < hc.num_elements; e++)
                    hc.x[e] = __float2half(c[mi][ni].x[e]);
                wmma::store_matrix_sync(&Clog[(size_t)ro * LPAD + co],
                                        hc, LPAD, wmma::mem_row_major);
            }
        }
}

// ============================================================================
// wmma tf32 GEMM (gates)
// ============================================================================
template <int BN>
__global__ void __launch_bounds__(256, 2)
gemm_tc(const float* __restrict__ A1, int lda1,
        const float* __restrict__ A2, int lda2,
        const int* __restrict__ gather_idx,
        const float* __restrict__ W1, int ldw1,
        const float* __restrict__ W2, int ldw2, int K1,
        float* __restrict__ C, int ldc,
        int N, int K) {
    extern __shared__ float smem[];
    float* As = smem;
    float* Ws = smem + NSTG * 128 * ASTR;

    const int tid = threadIdx.x;
    const int wid = tid >> 5;
    const int warp_m = wid >> 1;
    const int warp_n = wid & 1;
    const int n0 = blockIdx.x * BN;
    constexpr int WN = BN / 2;
    constexpr int NI = WN / 16;
    const int KT = K >> 5;

    const uint32_t as_base = (uint32_t)__cvta_generic_to_shared(As);
    const uint32_t ws_base = (uint32_t)__cvta_generic_to_shared(Ws);

    auto issue_stage = [&](int kt, int s) {
        const int kk = kt << 5;
        #pragma unroll
        for (int r = 0; r < 4; r++) {
            int f = tid + r * 256;
            int row = f >> 3, kq = f & 7;
            int k = kk + kq * 4;
            const float* src;
            if (k < K1) {
                int arow = gather_idx ? gather_idx[row] : row;
                src = A1 + (size_t)arow * lda1 + k;
            } else {
                src = A2 + (size_t)row * lda2 + (k - K1);
            }
            cp_async16(as_base + (uint32_t)((s * 128 + row) * ASTR + kq * 4) * 4, src);
        }
        #pragma unroll
        for (int r = 0; r < BN / 32; r++) {
            int f = tid + r * 256;
            int row = f >> 3, kq = f & 7;
            int k = kk + kq * 4;
            int nr = n0 + row;
            if (nr >= N) nr = N - 1;
            const float* src = (k < K1)
                ? W1 + (size_t)nr * ldw1 + k
                : W2 + (size_t)nr * ldw2 + (k - K1);
            cp_async16(ws_base + (uint32_t)((s * BN + row) * ASTR + kq * 4) * 4, src);
        }
        cp_commit();
    };

    wmma::fragment<wmma::accumulator, 16, 16, 8, float> c[2][NI];
    #pragma unroll
    for (int i = 0; i < 2; i++)
        #pragma unroll
        for (int j = 0; j < NI; j++) wmma::fill_fragment(c[i][j], 0.0f);

    issue_stage(0, 0);
    if (KT > 1) issue_stage(1, 1);

    for (int kt = 0; kt < KT; kt++) {
        if (kt + 2 < KT) {
            issue_stage(kt + 2, (kt + 2) % NSTG);
            cp_wait<2>();
        } else if (kt + 1 < KT) {
            cp_wait<1>();
        } else {
            cp_wait<0>();
        }
        __syncthreads();

        const int s = kt % NSTG;
        const float* as = As + (size_t)s * 128 * ASTR;
        const float* ws = Ws + (size_t)s * BN * ASTR;

        #pragma unroll
        for (int k8 = 0; k8 < 32; k8 += 8) {
            wmma::fragment<wmma::matrix_a, 16, 16, 8, wmma::precision::tf32,
                           wmma::row_major> a[2];
            wmma::fragment<wmma::matrix_b, 16, 16, 8, wmma::precision::tf32,
                           wmma::col_major> b[NI];
            #pragma unroll
            for (int mi = 0; mi < 2; mi++)
                wmma::load_matrix_sync(a[mi],
                    as + (warp_m * 32 + mi * 16) * ASTR + k8, ASTR);
            #pragma unroll
            for (int ni = 0; ni < NI; ni++)
                wmma::load_matrix_sync(b[ni],
                    ws + (warp_n * WN + ni * 16) * ASTR + k8, ASTR);
            #pragma unroll
            for (int mi = 0; mi < 2; mi++)
                #pragma unroll
                for (int ni = 0; ni < NI; ni++)
                    wmma::mma_sync(c[mi][ni], a[mi], b[ni], c[mi][ni]);
        }
        __syncthreads();
    }

    #pragma unroll
    for (int mi = 0; mi < 2; mi++)
        #pragma unroll
        for (int ni = 0; ni < NI; ni++)
            wmma::store_matrix_sync(
                &C[(size_t)(warp_m * 32 + mi * 16) * ldc + n0 + warp_n * WN + ni * 16],
                c[mi][ni], ldc, wmma::mem_row_major);
}

// ---------------- LSTM pointwise ----------------
__global__ void lstm_kernel(const float* __restrict__ c0,
                            const float* __restrict__ b_ih,
                            const float* __restrict__ b_hh,
                            float* __restrict__ h1_out,
                            float* __restrict__ c1_out) {
    int i = blockIdx.x * blockDim.x + threadIdx.x;
    if (i >= BB * HH) return;
    int b = i / HH, h = i % HH;
    const float* g = g_gates + (size_t)b * H4;
    float gi = g[h]          + b_ih[h]          + b_hh[h];
    float gf = g[HH + h]     + b_ih[HH + h]     + b_hh[HH + h];
    float gg = g[2 * HH + h] + b_ih[2 * HH + h] + b_hh[2 * HH + h];
    float go = g[3 * HH + h] + b_ih[3 * HH + h] + b_hh[3 * HH + h];
    float c = sigmoidf_(gf) * c0[i] + sigmoidf_(gi) * tanhf(gg);
    float hh = sigmoidf_(go) * tanhf(c);
    c1_out[i] = c;
    h1_out[i] = hh;
}

// ============================================================================
// Merged launch: flash attention (blocks [0, 2B)) + stats quarters (next 4B).
// ============================================================================
__global__ void __launch_bounds__(256)
flash_stats(const float* __restrict__ enc,
            const float* __restrict__ cenc,
            const float* __restrict__ attn_b,
            const float* __restrict__ cattn_b,
            const float* __restrict__ out_b) {
    extern __shared__ float fs[];
    const int tid = threadIdx.x;

    if (blockIdx.x < 2 * BB) {
        const int aid = blockIdx.x >> 7;
        const int b = blockIdx.x & 127;
        const int T = aid ? TC : TT;
        const int NC = (T + FCH - 1) / FCH;
        const float* eb = (aid ? cenc : enc) + (size_t)b * T * HH;

        float* sdec = fs + FS_SDEC;
        float* sraw = fs + FS_SRAW;
        float* sc   = fs + FS_SC;
        float* swc  = fs + FS_SWC;
        float* chunk = fs + FS_CHUNK;
        const uint32_t ch_base = (uint32_t)__cvta_generic_to_shared(chunk);

        {
            const float* dec = g_dec2 + (size_t)b * 1024 + aid * HH;
            const float* bias = aid ? cattn_b : attn_b;
            sdec[tid] = dec[tid] + bias[tid];
            sdec[tid + 256] = dec[tid + 256] + bias[tid + 256];
        }

        auto issue_chunk = [&](int c) {
            const int s = c & 1;
            const int t0 = c * FCH;
            #pragma unroll
            for (int r = 0; r < 8; r++) {
                int f = tid + r * 256;
                int row = f >> 7;
                int c4 = f & 127;
                int t = t0 + row;
                if (t >= T) t = T - 1;
                cp_async16(ch_base + (uint32_t)(s * FCH * HH + row * HH + c4 * 4) * 4,
                           eb + (size_t)t * HH + c4 * 4);
            }
            cp_commit();
        };

        issue_chunk(0);
        __syncthreads();

        float acc0 = 0.0f, acc1 = 0.0f;
        float m = -INFINITY, ssum = 0.0f;
        const int warp = tid >> 5, lane = tid & 31;

        for (int c = 0; c < NC; c++) {
            if (c + 1 < NC) {
                issue_chunk(c + 1);
                cp_wait<1>();
            } else {
                cp_wait<0>();
            }
            __syncthreads();

            const float* ch = chunk + (c & 1) * FCH * HH;
            const int t0 = c * FCH;

            #pragma unroll
            for (int rr = 0; rr < 2; rr++) {
                int row = warp + rr * 8;
                int t = t0 + row;
                const float4* rp = reinterpret_cast<const float4*>(ch + row * HH);
                float s = 0.0f;
                #pragma unroll
                for (int q = 0; q < 4; q++) {
                    int f4 = lane + 32 * q;
                    float4 v = rp[f4];
                    s += v.x * sdec[f4 * 4 + 0] + v.y * sdec[f4 * 4 + 1] +
                         v.z * sdec[f4 * 4 + 2] + v.w * sdec[f4 * 4 + 3];
                }
                #pragma unroll
                for (int o = 16; o > 0; o >>= 1)
                    s += __shfl_xor_sync(0xffffffffu, s, o);
                if (lane == 0) {
                    sc[row] = (t < T) ? s : -INFINITY;
                    if (t < T) sraw[t] = s;
                }
            }
            __syncthreads();

            float mc = sc[0];
            #pragma unroll
            for (int t = 1; t < FCH; t++) mc = fmaxf(mc, sc[t]);
            float newm = fmaxf(m, mc);
            if (tid < FCH)
                swc[tid] = (sc[tid] == -INFINITY) ? 0.0f : __expf(sc[tid] - newm);
            __syncthreads();

            float f = (m == -INFINITY) ? 0.0f : __expf(m - newm);
            acc0 *= f;
            acc1 *= f;
            float wsum = 0.0f;
            #pragma unroll
            for (int t = 0; t < FCH; t++) {
                float w = swc[t];
                wsum += w;
                acc0 += w * ch[t * HH + tid];
                acc1 += w * ch[t * HH + tid + 256];
            }
            ssum = ssum * f + wsum;
            m = newm;
            __syncthreads();
        }

        float inv = 1.0f / ssum;
        float* dst = aid ? g_cctx : g_context;
        dst[(size_t)b * HH + tid] = acc0 * inv;
        dst[(size_t)b * HH + tid + 256] = acc1 * inv;

        if (aid == 1) {
            if (tid < T) g_nscores[b][tid] = __expf(sraw[tid] - m) * inv;
        }
    } else {
        // ---- stats quarter: online (m, s) over half logits + bias ----
        const int idx = blockIdx.x - 2 * BB;
        const int q = idx & 3;
        const int b = idx >> 2;
        const int v0 = q * QSTAT;
        const int v1 = (q == 3) ? VV : v0 + QSTAT;
        const __half* lg = g_logits_h + (size_t)b * LPAD;
        float* red = fs;

        float m = -INFINITY, s = 0.0f;
        for (int v = v0 + tid; v < v1; v += 256) {
            float x = __half2float(lg[v]) + out_b[v];
            if (x > m) {
                s = s * __expf(m - x) + 1.0f;
                m = x;
            } else {
                s += __expf(x - m);
            }
        }
        float M = block_reduce(m, red, 0);
        s = (m == -INFINITY) ? 0.0f : s * __expf(m - M);
        float S = block_reduce(s, red, 1);
        if (tid == 0) {
            g_part[b][q][0] = M;
            g_part[b][q][1] = S;
        }
    }
}

// ============================================================================
// write: quarter-V-range prob + copy + log, with FUSED p_gen.
// grid (4, B), 256 threads. Each block recomputes its row's p_gen
// (deterministic, identical across the 4 blocks of a row).
// ============================================================================
__global__ void __launch_bounds__(256)
write_kernel(const float* __restrict__ out_b,
             const int* __restrict__ context_input,
             const float* __restrict__ h1,
             const float* __restrict__ embedding,
             const int* __restrict__ input,
             const float* __restrict__ gen_W,
             const float* __restrict__ gen_b,
             const float* __restrict__ sig_b,
             float* __restrict__ out) {
    extern __shared__ float copyv[];     // QWR floats + 32 red
    float* red = copyv + QWR;
    const int qq = blockIdx.x;
    const int b = blockIdx.y;
    const int tid = threadIdx.x;
    const int base = qq * QWR;
    const int len = (base + QWR <= VEXT) ? QWR : (VEXT - base);

    // ---- fused p_gen ----
    float s = 0.0f;
    for (int k = tid; k < HH; k += 256) {
        s += g_context[b * HH + k] * gen_W[k];
        s += g_cctx[b * HH + k] * gen_W[HH + k];
        s += h1[(size_t)b * HH + k] * gen_W[2 * HH + k];
    }
    {
        const float* emb = embedding + (size_t)input[b] * EE;
        for (int k = tid; k < EE; k += 256) s += emb[k] * gen_W[3 * HH + k];
    }
    s = block_reduce(s, red, 1);
    float cnt = 0.0f;
    for (int t = tid; t < TC; t += 256)
        cnt += (context_input[(size_t)b * TC + t] > 0) ? 1.0f : 0.0f;
    cnt = block_reduce(cnt, red, 1);
    float pg = sigmoidf_(s + gen_b[0] + sig_b[0]);
    if (cnt == 0.0f) pg = 1.0f;

    // ---- softmax scale from stats partials ----
    float M = fmaxf(fmaxf(g_part[b][0][0], g_part[b][1][0]),
                    fmaxf(g_part[b][2][0], g_part[b][3][0]));
    float S = g_part[b][0][1] * __expf(g_part[b][0][0] - M)
            + g_part[b][1][1] * __expf(g_part[b][1][0] - M)
            + g_part[b][2][1] * __expf(g_part[b][2][0] - M)
            + g_part[b][3][1] * __expf(g_part[b][3][0] - M);
    const float scale = pg / S;

    for (int v = tid; v < len; v += 256) copyv[v] = 0.0f;
    __syncthreads();

    if (tid < TC) {
        int idx = context_input[(size_t)b * TC + tid];
        if (idx >= base && idx < base + len) {
            float w = (1.0f - pg) * g_nscores[b][tid];
            atomicAdd(&copyv[idx - base], w);
        }
    }
    __syncthreads();

    const __half* lg = g_logits_h + (size_t)b * LPAD;
    float* row = out + (size_t)b * VEXT;

    const int vend = (base + len < VV) ? (base + len) : VV;
    for (int v = base + tid; v < vend; v += 256) {
        float p = __expf(__half2float(lg[v]) + out_b[v] - M) * scale + copyv[v - base];
        row[v] = __logf(fmaxf(p, 1e-10f));
    }
    for (int v = (VV > base ? VV : base) + tid; v < base + len; v += 256)
        row[v] = __logf(fmaxf(copyv[v - base], 1e-10f));
}

// ---------------- launcher ----------------
extern "C" void kernel_launch(void* const* d_in, const int* in_sizes, int n_in,
                              void* d_out, int out_size) {
    const int*   input    = (const int*)  d_in[0];
    const float* h0       = (const float*)d_in[1];
    const float* c0       = (const float*)d_in[2];
    const float* enc      = (const float*)d_in[3];
    const float* cenc     = (const float*)d_in[4];
    const int*   ctx_in   = (const int*)  d_in[5];
    const float* embedding= (const float*)d_in[6];
    const float* W_ih     = (const float*)d_in[7];
    const float* W_hh     = (const float*)d_in[8];
    const float* b_ih     = (const float*)d_in[9];
    const float* b_hh     = (const float*)d_in[10];
    const float* attn_W   = (const float*)d_in[11];
    const float* attn_b   = (const float*)d_in[12];
    const float* cattn_W  = (const float*)d_in[13];
    const float* cattn_b  = (const float*)d_in[14];
    const float* gen_W    = (const float*)d_in[15];
    const float* gen_b    = (const float*)d_in[16];
    const float* sig_b    = (const float*)d_in[17];
    const float* out_W    = (const float*)d_in[18];
    const float* out_b    = (const float*)d_in[19];

    float* out = (float*)d_out;
    float* logp   = out;
    float* h1_out = out + (size_t)BB * VEXT;
    float* c1_out = h1_out + (size_t)BB * HH;

    float*  d_gates;   cudaGetSymbolAddress((void**)&d_gates,   g_gates);
    float*  d_dec2;    cudaGetSymbolAddress((void**)&d_dec2,    g_dec2);
    __half* d_logits;  cudaGetSymbolAddress((void**)&d_logits,  g_logits_h);

    const int SMEM64    = NSTG * (128 + 64) * ASTR * 4;  // 82944
    const int SMEM_FL   = FS_TOTAL * 4;                  // 68736
    const int SMEM_WRITE = (QWR + 32) * 4;               // ~50180
    cudaFuncSetAttribute(gemm_tc<64>,
        cudaFuncAttributeMaxDynamicSharedMemorySize, SMEM64);
    cudaFuncSetAttribute(flash_stats,
        cudaFuncAttributeMaxDynamicSharedMemorySize, SMEM_FL);
    cudaFuncSetAttribute(write_kernel,
        cudaFuncAttributeMaxDynamicSharedMemorySize, SMEM_WRITE);

    // 1) gates = [emb | h0] @ [W_ih | W_hh]^T
    gemm_tc<64><<<H4 / 64, 256, SMEM64>>>(
        embedding, EE, h0, HH, input,
        W_ih, EE, W_hh, HH, EE,
        d_gates, H4, H4, EE + HH);

    // 2) LSTM pointwise -> h1, c1 (into d_out tail)
    lstm_kernel<<<(BB * HH + 255) / 256, 256>>>(c0, b_ih, b_hh, h1_out, c1_out);

    // 3) mega fp16 GEMM: logits (half out) + dec2 in one launch
    mega_fp16<<<NLOGIT + NDEC, 256>>>(h1_out, out_W, attn_W, cattn_W,
                                      d_logits, d_dec2);

    // 4) flash attention (enc read once) + softmax stats partials [ncu slot]
    flash_stats<<<2 * BB + 4 * BB, 256, SMEM_FL>>>(
        enc, cenc, attn_b, cattn_b, out_b);

    // 5) fused p_gen + prob + copy-scatter + log, quarter split
    write_kernel<<<dim3(4, BB), 256, SMEM_WRITE>>>(
        out_b, ctx_in, h1_out, embedding, input, gen_W, gen_b, sig_b, logp);
}